// round 14
// baseline (speedup 1.0000x reference)
#include <cuda_runtime.h>
#include <cstdint>

#define BB 4
#define NSEQ 2048
#define HH 768
#define NHEAD 12
#define HDIM 64
#define MM 16
#define NMB 128            // NSEQ / MM
#define BNROWS 8192        // BB * NSEQ
#define NCHAIN (BB * NHEAD)

// ---------------- scratch (static device globals: allocation-free) -------
__device__ float g_xqk  [BNROWS * HH];
__device__ float g_xvraw[BNROWS * HH];
__device__ float g_gate [BNROWS * HH];
__device__ float g_xq   [BNROWS * HH];   // [B][NH][NMB][M][HD]
__device__ float g_xk   [BNROWS * HH];
__device__ float g_xv   [BNROWS * HH];
__device__ float g_y    [BNROWS * HH];   // [B*N][768]
__device__ float g_tmp  [BNROWS * HH];
__device__ float g_lr   [NCHAIN * NMB * MM];
__device__ float g_zq   [NCHAIN * NMB * MM * HDIM];
__device__ float g_grad [NCHAIN * NMB * MM * HDIM];

__device__ __forceinline__ float gelu_tanh(float x) {
    const float c0 = 0.7978845608028654f;   // sqrt(2/pi)
    float x3 = x * x * x;
    return 0.5f * x * (1.0f + tanhf(c0 * (x + 0.044715f * x3)));
}

__device__ __forceinline__ void wred2(float& a, float& b) {
#pragma unroll
    for (int o = 16; o; o >>= 1) {
        a += __shfl_xor_sync(0xffffffffu, a, o);
        b += __shfl_xor_sync(0xffffffffu, b, o);
    }
}

__device__ __forceinline__ void wred4(float& a, float& b, float& c, float& d) {
#pragma unroll
    for (int o = 16; o; o >>= 1) {
        a += __shfl_xor_sync(0xffffffffu, a, o);
        b += __shfl_xor_sync(0xffffffffu, b, o);
        c += __shfl_xor_sync(0xffffffffu, c, o);
        d += __shfl_xor_sync(0xffffffffu, d, o);
    }
}

// ================== tf32 mma helpers ======================================
__device__ __forceinline__ uint32_t f2tf32(float x) {
    uint32_t r;
    asm("cvt.rna.tf32.f32 %0, %1;" : "=r"(r) : "f"(x));
    return r;
}

__device__ __forceinline__ void mma_tf32(float c[4], const uint32_t a[4],
                                         const uint32_t b[2]) {
    asm volatile(
        "mma.sync.aligned.m16n8k8.row.col.f32.tf32.tf32.f32 "
        "{%0,%1,%2,%3},{%4,%5,%6,%7},{%8,%9},{%0,%1,%2,%3};"
        : "+f"(c[0]), "+f"(c[1]), "+f"(c[2]), "+f"(c[3])
        : "r"(a[0]), "r"(a[1]), "r"(a[2]), "r"(a[3]), "r"(b[0]), "r"(b[1]));
}

__device__ __forceinline__ void cvt4(const float ar[4], uint32_t a[4]) {
#pragma unroll
    for (int i = 0; i < 4; i++) a[i] = f2tf32(ar[i]);
}

#define LDMX4(r, addr) \
    asm volatile("ldmatrix.sync.aligned.m8n8.x4.shared.b16 {%0,%1,%2,%3}, [%4];" \
        : "=r"((r)[0]), "=r"((r)[1]), "=r"((r)[2]), "=r"((r)[3]) : "r"(addr))

#define CPA16(dst, src) \
    asm volatile("cp.async.cg.shared.global [%0], [%1], 16;" :: "r"(dst), "l"(src))
#define CPCOMMIT() asm volatile("cp.async.commit_group;")
template <int N>
__device__ __forceinline__ void cpwait() {
    asm volatile("cp.async.wait_group %0;" :: "n"(N));
}

// ================== big GEMM (128x128x32, A=tf32, B=hi/lo tf32) ==========
// Works at 256 threads; at >256 threads, extra threads only hit barriers.
#define ASTRIDE 36
#define BSTRIDE 136
#define ASTAGE  (128 * ASTRIDE)
#define BSTAGE  (32 * BSTRIDE)
#define GEMM_SMEM ((2 * ASTAGE + 2 * BSTAGE) * 4)   // 71680 bytes

__device__ __forceinline__ void gemm_issue(
    const float* A, const float* W, int row0, int col0, int kb, int stage,
    uint32_t sA, uint32_t sB, int arow, int acol4, int brow, int bcol4)
{
    const float* ag = A + (size_t)(row0 + arow) * HH + kb * 32 + acol4;
    uint32_t ad = sA + (uint32_t)(stage * ASTAGE + arow * ASTRIDE + acol4) * 4u;
#pragma unroll
    for (int p = 0; p < 4; p++)
        CPA16(ad + p * 32 * ASTRIDE * 4, ag + (size_t)p * 32 * HH);
    const float* bg = W + (size_t)(kb * 32 + brow) * HH + col0 + bcol4;
    uint32_t bd = sB + (uint32_t)(stage * BSTAGE + brow * BSTRIDE + bcol4) * 4u;
#pragma unroll
    for (int p = 0; p < 4; p++)
        CPA16(bd + p * 8 * BSTRIDE * 4, bg + (size_t)p * 8 * HH);
    CPCOMMIT();
}

__device__ void gemm_body(const float* __restrict__ A,
                          const float* __restrict__ W,
                          float* __restrict__ C,
                          int bx, int by, int act)
{
    extern __shared__ float smem[];
    float* As = smem;
    float* Bs = smem + 2 * ASTAGE;

    int tid = threadIdx.x;
    bool on = tid < 256;
    int wid = tid >> 5, lane = tid & 31;
    int warp_m = wid & 1, warp_n = wid >> 1;
    int grp = lane >> 2, qid = lane & 3;
    int row0 = by * 128, col0 = bx * 128;

    int arow = tid >> 3, acol4 = (tid & 7) * 4;
    int brow = tid >> 5, bcol4 = (tid & 31) * 4;

    uint32_t sA = (uint32_t)__cvta_generic_to_shared(As);
    uint32_t sB = (uint32_t)__cvta_generic_to_shared(Bs);

    float c[4][4][4];
#pragma unroll
    for (int i = 0; i < 4; i++)
#pragma unroll
        for (int j = 0; j < 4; j++)
#pragma unroll
            for (int r = 0; r < 4; r++) c[i][j][r] = 0.0f;

    if (on)
        gemm_issue(A, W, row0, col0, 0, 0, sA, sB, arow, acol4, brow, bcol4);

    int stage = 0;
    for (int kb = 0; kb < HH / 32; kb++) {
        if (kb + 1 < HH / 32) {
            if (on)
                gemm_issue(A, W, row0, col0, kb + 1, stage ^ 1, sA, sB,
                           arow, acol4, brow, bcol4);
            cpwait<1>();
        } else {
            cpwait<0>();
        }
        __syncthreads();

        if (on) {
            const float* as = As + stage * ASTAGE + (warp_m * 64) * ASTRIDE;
            const float* bs = Bs + stage * BSTAGE + warp_n * 32;

#pragma unroll
            for (int ks = 0; ks < 4; ks++) {
                const int k = ks * 8;
                uint32_t bhi[4][2], blo[4][2];
#pragma unroll
                for (int nj = 0; nj < 4; nj++) {
#pragma unroll
                    for (int r = 0; r < 2; r++) {
                        float v = bs[(k + qid + r * 4) * BSTRIDE + nj * 8 + grp];
                        uint32_t hbits = f2tf32(v);
                        bhi[nj][r] = hbits;
                        blo[nj][r] = f2tf32(v - __uint_as_float(hbits));
                    }
                }
#pragma unroll
                for (int mi = 0; mi < 4; mi++) {
                    float ar[4];
                    ar[0] = as[(mi * 16 + grp) * ASTRIDE + k + qid];
                    ar[1] = as[(mi * 16 + grp + 8) * ASTRIDE + k + qid];
                    ar[2] = as[(mi * 16 + grp) * ASTRIDE + k + qid + 4];
                    ar[3] = as[(mi * 16 + grp + 8) * ASTRIDE + k + qid + 4];
                    uint32_t ah[4];
                    cvt4(ar, ah);
#pragma unroll
                    for (int nj = 0; nj < 4; nj++) {
                        mma_tf32(c[mi][nj], ah, blo[nj]);
                        mma_tf32(c[mi][nj], ah, bhi[nj]);
                    }
                }
            }
        }
        __syncthreads();
        stage ^= 1;
    }

    if (on) {
#pragma unroll
        for (int mi = 0; mi < 4; mi++) {
            int r0 = row0 + warp_m * 64 + mi * 16 + grp;
#pragma unroll
            for (int nj = 0; nj < 4; nj++) {
                int cc = col0 + warp_n * 32 + nj * 8 + 2 * qid;
                float v0 = c[mi][nj][0], v1 = c[mi][nj][1];
                float v2 = c[mi][nj][2], v3 = c[mi][nj][3];
                if (act) {
                    v0 = gelu_tanh(v0); v1 = gelu_tanh(v1);
                    v2 = gelu_tanh(v2); v3 = gelu_tanh(v3);
                }
                *(float2*)(C + (size_t)r0 * HH + cc) = make_float2(v0, v1);
                *(float2*)(C + (size_t)(r0 + 8) * HH + cc) = make_float2(v2, v3);
            }
        }
    }
}

__global__ __launch_bounds__(256) void gemm_tc(
    const float* __restrict__ W,
    const float* __restrict__ Aext,
    float*       Cext,
    int srcsel, int dstsel, int act)
{
    const float* A = (srcsel == 0) ? Aext : g_tmp;
    float* C = (dstsel == 0) ? g_xqk :
               (dstsel == 1) ? g_xvraw :
               (dstsel == 2) ? g_gate : Cext;
    gemm_body(A, W, C, blockIdx.x, blockIdx.y, act);
}

// combined wq+wv gemm: grid (12, 64)
__global__ __launch_bounds__(256) void gemm_qv(
    const float* __restrict__ hs,
    const float* __restrict__ wq,
    const float* __restrict__ wv)
{
    int bx = blockIdx.x;
    if (bx < 6) gemm_body(hs, wq, g_xqk, bx, blockIdx.y, 0);
    else        gemm_body(hs, wv, g_xvraw, bx - 6, blockIdx.y, 0);
}

// ------- causal conv (K=4) + RoPE + permute + lr, 4 rows per block -------
__global__ __launch_bounds__(384) void convrope_kernel(
    const int*   __restrict__ pids,
    const float* __restrict__ cqk, const float* __restrict__ cqb,
    const float* __restrict__ ckk, const float* __restrict__ ckb,
    const float* __restrict__ hs,
    const float* __restrict__ lrw, const float* __restrict__ lrb)
{
    __shared__ float sxh[4][HH];
    int blk = blockIdx.x;
    int tid = threadIdx.x;
    int b = blk >> 9;
    int t0 = (blk & 511) * 4;
    int c = tid * 2;

#pragma unroll
    for (int r = 0; r < 4; r++) {
        size_t ro = (size_t)(b * NSEQ + t0 + r) * HH;
        sxh[r][tid]       = hs[ro + tid];
        sxh[r][tid + 384] = hs[ro + tid + 384];
    }

    float wq0[4], wq1[4], wk0[4], wk1[4];
#pragma unroll
    for (int j = 0; j < 4; j++) {
        wq0[j] = cqk[j * HH + c];
        wq1[j] = cqk[j * HH + c + 1];
        wk0[j] = ckk[j * HH + c];
        wk1[j] = ckk[j * HH + c + 1];
    }
    float bq0 = cqb[c], bq1 = cqb[c + 1];
    float bk0 = ckb[c], bk1 = ckb[c + 1];

    int h = c / 64;
    int d = c & 63;
    int f = d >> 1;
    float theta = expf(-(float)f * (9.210340371976184f / 32.0f));

#pragma unroll
    for (int r = 0; r < 4; r++) {
        int t = t0 + r;
        float q0 = bq0, q1 = bq1, k0 = bk0, k1 = bk1;
#pragma unroll
        for (int j = 0; j < 4; j++) {
            int src = t - 4 + j;
            if (src >= 0) {
                const float* xr = g_xqk + ((size_t)(b * NSEQ + src)) * HH + c;
                float x0 = xr[0], x1 = xr[1];
                q0 = fmaf(x0, wq0[j], q0);
                q1 = fmaf(x1, wq1[j], q1);
                k0 = fmaf(x0, wk0[j], k0);
                k1 = fmaf(x1, wk1[j], k1);
            }
        }

        int pid = pids[b * NSEQ + t];
        int rr = ((pid % MM) + MM) % MM;
        float ang = (float)rr * theta;
        float sn, cs;
        sincosf(ang, &sn, &cs);

        float xq0 = q0 * cs - q1 * sn, xq1 = q0 * sn + q1 * cs;
        float xk0 = k0 * cs - k1 * sn, xk1 = k0 * sn + k1 * cs;

        int n = t >> 4, m = t & 15;
        size_t o = ((((size_t)b * NHEAD + h) * NMB + n) * MM + m) * HDIM + d;
        g_xq[o] = xq0; g_xq[o + 1] = xq1;
        g_xk[o] = xk0; g_xk[o + 1] = xk1;
        size_t vi = (size_t)(b * NSEQ + t) * HH + c;
        g_xv[o]     = g_xvraw[vi];
        g_xv[o + 1] = g_xvraw[vi + 1];
    }

    __syncthreads();
    int w = tid >> 5, lane = tid & 31;
    const float* ww = lrw + (size_t)w * HH;
    float s0 = 0.0f, s1 = 0.0f, s2 = 0.0f, s3 = 0.0f;
#pragma unroll 6
    for (int dd = lane; dd < HH; dd += 32) {
        float wv = ww[dd];
        s0 = fmaf(sxh[0][dd], wv, s0);
        s1 = fmaf(sxh[1][dd], wv, s1);
        s2 = fmaf(sxh[2][dd], wv, s2);
        s3 = fmaf(sxh[3][dd], wv, s3);
    }
    wred4(s0, s1, s2, s3);
    if (lane == 0) {
        float lb = lrb[w];
#pragma unroll
        for (int r = 0; r < 4; r++) {
            float sv = (r == 0) ? s0 : (r == 1) ? s1 : (r == 2) ? s2 : s3;
            float v = 1.0f / (1.0f + expf(-(sv + lb)));
            int t = t0 + r;
            int n = t >> 4, m = t & 15;
            g_lr[(((size_t)b * NHEAD + w) * NMB + n) * MM + m] = v;
        }
    }
}

// ======= tensor-core TTT scan, 512 threads, warp-group specialized =======
#define SWST 66
#define SGST 66
#define STS2 68
#define TILEF (16 * STS2)
#define STAGEF (3 * TILEF)

__device__ __forceinline__ void scan_prefetch512(
    const float* pk, const float* pq, const float* pv, const float* plr,
    int n, int st, uint32_t stile_u, uint32_t slr_u, int tid)
{
    int r = tid & 255;
    int row = r >> 4, col = (r & 15) * 4;
    int gi = n * 1024 + row * 64 + col;
    uint32_t dst = stile_u + (uint32_t)(st * STAGEF + row * STS2 + col) * 4u;
    if (tid < 256) {
        CPA16(dst,                 pk + gi);
        CPA16(dst + 2 * TILEF * 4, pv + gi);
    } else {
        CPA16(dst + TILEF * 4,     pq + gi);
    }
    if (tid < 4) CPA16(slr_u + (uint32_t)(st * 16 + tid * 4) * 4u,
                       plr + n * 16 + tid * 4);
    CPCOMMIT();
}

__device__ void scan_body_tc(int bh,
    const float* __restrict__ W1_0, const float* __restrict__ b1_0,
    const float* __restrict__ gamma, const float* __restrict__ beta,
    const float* __restrict__ lti)
{
    extern __shared__ float sm[];
    float*  sWp   = sm;                        // [64][66]
    float*  sgl   = sWp + 64 * SWST;           // [16][66]
    float*  stile = sgl + 16 * SGST;           // 2 stages x (xk,xq,xv)
    float*  slr2  = stile + 2 * STAGEF;        // [2][16]
    float*  szk   = slr2 + 32;                 // [16][68] zk transpose
    float*  sb1   = szk + 16 * STS2;           // [64]

    int h = bh % NHEAD;
    int tid = threadIdx.x;
    int w = tid >> 5, lane = tid & 31;     // w: 0..15
    int wg = w >> 3;                        // 0: zk/W-owner, 1: zq
    int wl = w & 7;
    int grp = lane >> 2, qid = lane & 3;
    int col0 = 8 * wl + 2 * qid;
    int m = w;                              // LN row (one per warp)
    int e = 2 * lane;

    float wacc[4][4];
    if (wg == 0) {
#pragma unroll
        for (int mt = 0; mt < 4; mt++) {
            float2 v0 = *(const float2*)&W1_0[(size_t)h * 4096 + (16 * mt + grp) * 64 + col0];
            float2 v1 = *(const float2*)&W1_0[(size_t)h * 4096 + (16 * mt + grp + 8) * 64 + col0];
            wacc[mt][0] = v0.x; wacc[mt][1] = v0.y;
            wacc[mt][2] = v1.x; wacc[mt][3] = v1.y;
        }
    }
    if (tid < 64) sb1[tid] = b1_0[h * 64 + tid];
    float gR0 = gamma[h * 64 + e], gR1 = gamma[h * 64 + e + 1];
    float btR0 = beta[h * 64 + e], btR1 = beta[h * 64 + e + 1];
    float ls = fmaxf(lti[15] + (1.0f / 16.0f), 0.0f) * (1.0f / 64.0f);

    const float* pk = g_xk + (size_t)bh * NMB * 1024;
    const float* pq = g_xq + (size_t)bh * NMB * 1024;
    const float* pv = g_xv + (size_t)bh * NMB * 1024;
    const float* plr = g_lr + (size_t)bh * NMB * 16;
    uint32_t stile_u = (uint32_t)__cvta_generic_to_shared(stile);
    uint32_t slr_u   = (uint32_t)__cvta_generic_to_shared(slr2);

    uint32_t aoff = (uint32_t)((lane & 15) * STS2 + (lane >> 4) * 4) * 4u;

    scan_prefetch512(pk, pq, pv, plr, 0, 0, stile_u, slr_u, tid);

    for (int n = 0; n < NMB; n++) {
        int st = n & 1;
        if (wg == 0) {
#pragma unroll
            for (int mt = 0; mt < 4; mt++) {
                *(float2*)&sWp[(16 * mt + grp) * SWST + col0] =
                    make_float2(wacc[mt][0], wacc[mt][1]);
                *(float2*)&sWp[(16 * mt + grp + 8) * SWST + col0] =
                    make_float2(wacc[mt][2], wacc[mt][3]);
            }
        }
        cpwait<0>();
        __syncthreads();                                   // sync1
        if (n + 1 < NMB)
            scan_prefetch512(pk, pq, pv, plr, n + 1, st ^ 1, stile_u, slr_u, tid);

        float* sxk = stile + st * STAGEF;
        float* sxv = sxk + 2 * TILEF;
        uint32_t sxk_u = stile_u + (uint32_t)(st * STAGEF) * 4u;
        uint32_t src_u = (wg == 0) ? sxk_u : (sxk_u + TILEF * 4u);

        // ---- wg0: Z1 = xk@W ; wg1: Zq = xq@W (A via ldmatrix.x4) ----
        float zh[4] = {0, 0, 0, 0}, zl[4] = {0, 0, 0, 0};
#pragma unroll
        for (int kt = 0; kt < 8; kt++) {
            int k = 8 * kt;
            float b0r = sWp[(k + qid) * SWST + 8 * wl + grp];
            float b1r = sWp[(k + qid + 4) * SWST + 8 * wl + grp];
            uint32_t bhi[2], blo[2];
            bhi[0] = f2tf32(b0r); blo[0] = f2tf32(b0r - __uint_as_float(bhi[0]));
            bhi[1] = f2tf32(b1r); blo[1] = f2tf32(b1r - __uint_as_float(bhi[1]));
            uint32_t araw[4], ah[4];
            LDMX4(araw, src_u + aoff + k * 4);
#pragma unroll
            for (int i = 0; i < 4; i++) ah[i] = f2tf32(__uint_as_float(araw[i]));
            mma_tf32(zl, ah, blo); mma_tf32(zh, ah, bhi);
        }
        float bb0 = sb1[col0], bb1 = sb1[col0 + 1];
        float z0 = zh[0] + zl[0] + bb0, z1 = zh[1] + zl[1] + bb1;
        float z2 = zh[2] + zl[2] + bb0, z3 = zh[3] + zl[3] + bb1;

        size_t base = ((size_t)bh * NMB + n) * 1024;
        if (wg == 0) {
            *(float2*)&szk[grp * STS2 + col0]       = make_float2(z0, z1);
            *(float2*)&szk[(grp + 8) * STS2 + col0] = make_float2(z2, z3);
        } else {
            *(float2*)&g_zq[base + grp * 64 + col0]       = make_float2(z0, z1);
            *(float2*)&g_zq[base + (grp + 8) * 64 + col0] = make_float2(z2, z3);
        }
        __syncthreads();                                   // sync2

        // ---- warp-local LN-L2 backward: warp w owns row m = w ----
        float2 za = *(const float2*)&szk[m * STS2 + e];
        float s1a = za.x + za.y, s2a = za.x * za.x + za.y * za.y;
        wred2(s1a, s2a);
        float mu0 = s1a * (1.0f / 64.0f);
        float rs0 = rsqrtf(s2a * (1.0f / 64.0f) - mu0 * mu0 + 1e-5f);
        float xh00 = (za.x - mu0) * rs0, xh01 = (za.y - mu0) * rs0;
        float2 xv0 = *(const float2*)&sxv[m * STS2 + e];
        float2 xk0v = *(const float2*)&sxk[m * STS2 + e];
        float gy00 = (fmaf(gR0, xh00, btR0) - (xv0.x - xk0v.x)) * gR0;
        float gy01 = (fmaf(gR1, xh01, btR1) - (xv0.y - xk0v.y)) * gR1;
        float t1a = gy00 + gy01, t2a = gy00 * xh00 + gy01 * xh01;
        wred2(t1a, t2a);
        float sc0 = rs0 * (1.0f / 64.0f);
        float gr00 = (64.0f * gy00 - t1a - xh00 * t2a) * sc0;
        float gr01 = (64.0f * gy01 - t1a - xh01 * t2a) * sc0;

        *(float2*)&g_grad[base + m * 64 + e] = make_float2(gr00, gr01);

        float lr0 = ls * slr2[st * 16 + m];
        *(float2*)&sgl[m * SGST + e] = make_float2(-lr0 * gr00, -lr0 * gr01);
        __syncthreads();                                   // sync3

        // ---- wg0: W += xk^T @ sgl ; warps 8-9: b1 += colsums(sgl) ----
        if (wg == 0) {
#pragma unroll
            for (int kt = 0; kt < 2; kt++) {
                int k = 8 * kt;
                float b0r = sgl[(k + qid) * SGST + 8 * wl + grp];
                float b1r = sgl[(k + qid + 4) * SGST + 8 * wl + grp];
                uint32_t bhi[2], blo[2];
                bhi[0] = f2tf32(b0r); blo[0] = f2tf32(b0r - __uint_as_float(bhi[0]));
                bhi[1] = f2tf32(b1r); blo[1] = f2tf32(b1r - __uint_as_float(bhi[1]));
#pragma unroll
                for (int mt = 0; mt < 4; mt++) {
                    float ar[4];
                    uint32_t ah[4];
                    ar[0] = sxk[(k + qid) * STS2 + 16 * mt + grp];
                    ar[1] = sxk[(k + qid) * STS2 + 16 * mt + grp + 8];
                    ar[2] = sxk[(k + qid + 4) * STS2 + 16 * mt + grp];
                    ar[3] = sxk[(k + qid + 4) * STS2 + 16 * mt + grp + 8];
                    cvt4(ar, ah);
                    mma_tf32(wacc[mt], ah, blo);
                    mma_tf32(wacc[mt], ah, bhi);
                }
            }
        } else if (tid >= 256 && tid < 320) {
            int ee = tid - 256;
            float s = 0.0f;
#pragma unroll
            for (int mm2 = 0; mm2 < 16; mm2++) s += sgl[mm2 * SGST + ee];
            sb1[ee] += s;
        }
    }
}

// ------- fused: 148 CTAs x 512 thr = 48 scan (dedicated SMs) + 100 gemm ---
__global__ __launch_bounds__(512) void fused_scan_gate(
    const float* __restrict__ hs, const float* __restrict__ wg_,
    const float* __restrict__ W1_0, const float* __restrict__ b1_0,
    const float* __restrict__ gamma, const float* __restrict__ beta,
    const float* __restrict__ lti)
{
    if (blockIdx.x < NCHAIN) {
        scan_body_tc(blockIdx.x, W1_0, b1_0, gamma, beta, lti);
    } else {
        for (int t = blockIdx.x - NCHAIN; t < 384; t += 100)
            gemm_body(hs, wg_, g_gate, t % 6, t / 6, 1);
    }
}

// ---------------- parallel epilogue: y = xq + LN(Zq - coef@grad) ----------
__global__ __launch_bounds__(256) void epilogue_y(
    const float* __restrict__ gamma, const float* __restrict__ beta,
    const float* __restrict__ lti)
{
    int blk = blockIdx.x;
    int bh = blk >> 7;
    int n  = blk & 127;
    int b = bh / NHEAD, h = bh % NHEAD;

    __shared__ float sxq[16 * STS2], sxk[16 * STS2], sgr[16 * STS2];
    __shared__ float szq[16 * 64];
    __shared__ float scoef[256], stok[16], slr[16], sg[64], sbt[64];

    int tid = threadIdx.x;
    int row = tid >> 4, col = (tid & 15) * 4;
    size_t base = ((size_t)bh * NMB + n) * 1024;
    int gi = row * 64 + col;
    *(float4*)&sxq[row * STS2 + col] =
        *(const float4*)&g_xq[(size_t)bh * NMB * 1024 + n * 1024 + gi];
    *(float4*)&sxk[row * STS2 + col] =
        *(const float4*)&g_xk[(size_t)bh * NMB * 1024 + n * 1024 + gi];
    *(float4*)&sgr[row * STS2 + col] = *(const float4*)&g_grad[base + gi];
    *(float4*)&szq[gi]               = *(const float4*)&g_zq[base + gi];
    if (tid < 16) {
        stok[tid] = fmaxf(lti[tid] + 1.0f / (float)(tid + 1), 0.0f);
        slr[tid]  = g_lr[(size_t)bh * NMB * 16 + n * 16 + tid];
    }
    if (tid < 64) {
        sg[tid]  = gamma[h * 64 + tid];
        sbt[tid] = beta[h * 64 + tid];
    }
    __syncthreads();

    {
        int mm = tid >> 4, nn = tid & 15;
        float a = 0.0f;
#pragma unroll
        for (int d = 0; d < 64; d += 4) {
            float4 qv = *(const float4*)&sxq[mm * STS2 + d];
            float4 kv = *(const float4*)&sxk[nn * STS2 + d];
            a = fmaf(qv.x, kv.x, a);
            a = fmaf(qv.y, kv.y, a);
            a = fmaf(qv.z, kv.z, a);
            a = fmaf(qv.w, kv.w, a);
        }
        scoef[tid] = (nn <= mm)
            ? stok[mm] * slr[nn] * (1.0f / 64.0f) * (a + 1.0f)
            : 0.0f;
    }
    __syncthreads();

    int w = tid >> 5, lane = tid & 31;
    int m0 = 2 * w, m1 = 2 * w + 1;
    int e = 2 * lane;
    float2 z0 = *(const float2*)&szq[m0 * 64 + e];
    float2 z1 = *(const float2*)&szq[m1 * 64 + e];
    float zq00 = z0.x, zq01 = z0.y, zq10 = z1.x, zq11 = z1.y;
#pragma unroll
    for (int nn = 0; nn < 16; nn++) {
        float c0 = scoef[m0 * 16 + nn];
        float c1 = scoef[m1 * 16 + nn];
        float2 gv = *(const float2*)&sgr[nn * STS2 + e];
        zq00 = fmaf(-c0, gv.x, zq00); zq01 = fmaf(-c0, gv.y, zq01);
        zq10 = fmaf(-c1, gv.x, zq10); zq11 = fmaf(-c1, gv.y, zq11);
    }
    float s1a = zq00 + zq01, s2a = zq00 * zq00 + zq01 * zq01;
    float s1b = zq10 + zq11, s2b = zq10 * zq10 + zq11 * zq11;
    wred4(s1a, s2a, s1b, s2b);
    float mu0 = s1a * (1.0f / 64.0f);
    float rs0 = rsqrtf(s2a * (1.0f / 64.0f) - mu0 * mu0 + 1e-5f);
    float mu1 = s1b * (1.0f / 64.0f);
    float rs1 = rsqrtf(s2b * (1.0f / 64.0f) - mu1 * mu1 + 1e-5f);
    float g0 = sg[e], g1 = sg[e + 1], bt0 = sbt[e], bt1 = sbt[e + 1];
    float2 qx0 = *(const float2*)&sxq[m0 * STS2 + e];
    float2 qx1 = *(const float2*)&sxq[m1 * STS2 + e];
    float y00 = qx0.x + fmaf((zq00 - mu0) * rs0, g0, bt0);
    float y01 = qx0.y + fmaf((zq01 - mu0) * rs0, g1, bt1);
    float y10 = qx1.x + fmaf((zq10 - mu1) * rs1, g0, bt0);
    float y11 = qx1.y + fmaf((zq11 - mu1) * rs1, g1, bt1);
    size_t or0 = ((size_t)(b * NSEQ + n * MM + m0)) * HH + h * HDIM + e;
    size_t or1 = ((size_t)(b * NSEQ + n * MM + m1)) * HH + h * HDIM + e;
    *(float2*)&g_y[or0] = make_float2(y00, y01);
    *(float2*)&g_y[or1] = make_float2(y10, y11);
}

// ---------------- post-norm + gate multiply ------------------------------
__global__ __launch_bounds__(256) void postnorm_kernel(
    const float* __restrict__ pns, const float* __restrict__ pnb)
{
    int row = blockIdx.x;
    const float* y = g_y + (size_t)row * HH;
    float v[3];
    float s1 = 0.0f, s2 = 0.0f;
#pragma unroll
    for (int i = 0; i < 3; i++) {
        v[i] = y[threadIdx.x + i * 256];
        s1 += v[i];
        s2 += v[i] * v[i];
    }
    wred2(s1, s2);
    __shared__ float r1[8], r2[8];
    int wid = threadIdx.x >> 5, ln = threadIdx.x & 31;
    if (ln == 0) { r1[wid] = s1; r2[wid] = s2; }
    __syncthreads();
    float a = 0.0f, bsum = 0.0f;
#pragma unroll
    for (int i = 0; i < 8; i++) { a += r1[i]; bsum += r2[i]; }
    float mu = a * (1.0f / 768.0f);
    float rstd = rsqrtf(bsum * (1.0f / 768.0f) - mu * mu + 1e-5f);
#pragma unroll
    for (int i = 0; i < 3; i++) {
        int c = threadIdx.x + i * 256;
        float z = fmaf((v[i] - mu) * rstd, pns[c], pnb[c]);
        g_tmp[(size_t)row * HH + c] = g_gate[(size_t)row * HH + c] * z;
    }
}

// ---------------- launch --------------------------------------------------
extern "C" void kernel_launch(void* const* d_in, const int* in_sizes, int n_in,
                              void* d_out, int out_size)
{
    const float* hs  = (const float*)d_in[0];
    const int*   pid = (const int*)  d_in[1];
    const float* wq  = (const float*)d_in[2];
    const float* wv  = (const float*)d_in[3];
    const float* wo  = (const float*)d_in[4];
    const float* wg  = (const float*)d_in[5];
    const float* cqk = (const float*)d_in[6];
    const float* cqb = (const float*)d_in[7];
    const float* ckk = (const float*)d_in[8];
    const float* ckb = (const float*)d_in[9];
    const float* lrw = (const float*)d_in[10];
    const float* lrb = (const float*)d_in[11];
    const float* lti = (const float*)d_in[12];
    const float* gam = (const float*)d_in[13];
    const float* bet = (const float*)d_in[14];
    const float* pns = (const float*)d_in[15];
    const float* pnb = (const float*)d_in[16];
    const float* W10 = (const float*)d_in[17];
    const float* b10 = (const float*)d_in[18];
    float* out = (float*)d_out;

    cudaFuncSetAttribute(gemm_tc, cudaFuncAttributeMaxDynamicSharedMemorySize,
                         GEMM_SMEM);
    cudaFuncSetAttribute(gemm_qv, cudaFuncAttributeMaxDynamicSharedMemorySize,
                         GEMM_SMEM);
    cudaFuncSetAttribute(fused_scan_gate,
                         cudaFuncAttributeMaxDynamicSharedMemorySize, GEMM_SMEM);

    dim3 qvgrid(12, BNROWS / 128);       // wq + wv combined
    dim3 ggrid(HH / 128, BNROWS / 128);  // (6, 64)

    gemm_qv<<<qvgrid, 256, GEMM_SMEM>>>(hs, wq, wv);

    convrope_kernel<<<BNROWS / 4, 384>>>(pid, cqk, cqb, ckk, ckb, hs, lrw, lrb);

    fused_scan_gate<<<148, 512, GEMM_SMEM>>>(hs, wg, W10, b10, gam, bet, lti);

    epilogue_y<<<NCHAIN * NMB, 256>>>(gam, bet, lti);

    postnorm_kernel<<<BNROWS, 256>>>(pns, pnb);

    gemm_tc<<<ggrid, 256, GEMM_SMEM>>>(wo, nullptr, out, 1, 3, 0);  // final
}

// round 15
// speedup vs baseline: 1.1108x; 1.1108x over previous
#include <cuda_runtime.h>
#include <cstdint>

#define BB 4
#define NSEQ 2048
#define HH 768
#define NHEAD 12
#define HDIM 64
#define MM 16
#define NMB 128            // NSEQ / MM
#define BNROWS 8192        // BB * NSEQ
#define NCHAIN (BB * NHEAD)

// ---------------- scratch (static device globals: allocation-free) -------
__device__ float g_xqk  [BNROWS * HH];
__device__ float g_xvraw[BNROWS * HH];
__device__ float g_gate [BNROWS * HH];
__device__ float g_xq   [BNROWS * HH];   // [B][NH][NMB][M][HD]
__device__ float g_xk   [BNROWS * HH];
__device__ float g_xv   [BNROWS * HH];
__device__ float g_y    [BNROWS * HH];   // [B*N][768]
__device__ float g_tmp  [BNROWS * HH];
__device__ float g_lr   [NCHAIN * NMB * MM];
__device__ float g_zq   [NCHAIN * NMB * MM * HDIM];
__device__ float g_grad [NCHAIN * NMB * MM * HDIM];

__device__ __forceinline__ float gelu_tanh(float x) {
    const float c0 = 0.7978845608028654f;   // sqrt(2/pi)
    float x3 = x * x * x;
    return 0.5f * x * (1.0f + tanhf(c0 * (x + 0.044715f * x3)));
}

__device__ __forceinline__ void wred2(float& a, float& b) {
#pragma unroll
    for (int o = 16; o; o >>= 1) {
        a += __shfl_xor_sync(0xffffffffu, a, o);
        b += __shfl_xor_sync(0xffffffffu, b, o);
    }
}

__device__ __forceinline__ void wred4(float& a, float& b, float& c, float& d) {
#pragma unroll
    for (int o = 16; o; o >>= 1) {
        a += __shfl_xor_sync(0xffffffffu, a, o);
        b += __shfl_xor_sync(0xffffffffu, b, o);
        c += __shfl_xor_sync(0xffffffffu, c, o);
        d += __shfl_xor_sync(0xffffffffu, d, o);
    }
}

// ================== tf32 mma helpers ======================================
__device__ __forceinline__ uint32_t f2tf32(float x) {
    uint32_t r;
    asm("cvt.rna.tf32.f32 %0, %1;" : "=r"(r) : "f"(x));
    return r;
}

__device__ __forceinline__ void mma_tf32(float c[4], const uint32_t a[4],
                                         const uint32_t b[2]) {
    asm volatile(
        "mma.sync.aligned.m16n8k8.row.col.f32.tf32.tf32.f32 "
        "{%0,%1,%2,%3},{%4,%5,%6,%7},{%8,%9},{%0,%1,%2,%3};"
        : "+f"(c[0]), "+f"(c[1]), "+f"(c[2]), "+f"(c[3])
        : "r"(a[0]), "r"(a[1]), "r"(a[2]), "r"(a[3]), "r"(b[0]), "r"(b[1]));
}

__device__ __forceinline__ void cvt4(const float ar[4], uint32_t a[4]) {
#pragma unroll
    for (int i = 0; i < 4; i++) a[i] = f2tf32(ar[i]);
}

#define LDMX4(r, addr) \
    asm volatile("ldmatrix.sync.aligned.m8n8.x4.shared.b16 {%0,%1,%2,%3}, [%4];" \
        : "=r"((r)[0]), "=r"((r)[1]), "=r"((r)[2]), "=r"((r)[3]) : "r"(addr))

#define CPA16(dst, src) \
    asm volatile("cp.async.cg.shared.global [%0], [%1], 16;" :: "r"(dst), "l"(src))
#define CPCOMMIT() asm volatile("cp.async.commit_group;")
template <int N>
__device__ __forceinline__ void cpwait() {
    asm volatile("cp.async.wait_group %0;" :: "n"(N));
}

// ================== big GEMM (128x128x32, A=tf32, B=hi/lo tf32) ==========
#define ASTRIDE 36
#define BSTRIDE 136
#define ASTAGE  (128 * ASTRIDE)
#define BSTAGE  (32 * BSTRIDE)
#define GEMM_SMEM ((2 * ASTAGE + 2 * BSTAGE) * 4)   // 71680 bytes

__device__ __forceinline__ void gemm_issue(
    const float* A, const float* W, int row0, int col0, int kb, int stage,
    uint32_t sA, uint32_t sB, int arow, int acol4, int brow, int bcol4)
{
    const float* ag = A + (size_t)(row0 + arow) * HH + kb * 32 + acol4;
    uint32_t ad = sA + (uint32_t)(stage * ASTAGE + arow * ASTRIDE + acol4) * 4u;
#pragma unroll
    for (int p = 0; p < 4; p++)
        CPA16(ad + p * 32 * ASTRIDE * 4, ag + (size_t)p * 32 * HH);
    const float* bg = W + (size_t)(kb * 32 + brow) * HH + col0 + bcol4;
    uint32_t bd = sB + (uint32_t)(stage * BSTAGE + brow * BSTRIDE + bcol4) * 4u;
#pragma unroll
    for (int p = 0; p < 4; p++)
        CPA16(bd + p * 8 * BSTRIDE * 4, bg + (size_t)p * 8 * HH);
    CPCOMMIT();
}

__device__ void gemm_body(const float* __restrict__ A,
                          const float* __restrict__ W,
                          float* __restrict__ C,
                          int bx, int by, int act)
{
    extern __shared__ float smem[];
    float* As = smem;
    float* Bs = smem + 2 * ASTAGE;

    int tid = threadIdx.x;
    int wid = tid >> 5, lane = tid & 31;
    int warp_m = wid & 1, warp_n = wid >> 1;
    int grp = lane >> 2, qid = lane & 3;
    int row0 = by * 128, col0 = bx * 128;

    int arow = tid >> 3, acol4 = (tid & 7) * 4;
    int brow = tid >> 5, bcol4 = (tid & 31) * 4;

    uint32_t sA = (uint32_t)__cvta_generic_to_shared(As);
    uint32_t sB = (uint32_t)__cvta_generic_to_shared(Bs);

    float c[4][4][4];
#pragma unroll
    for (int i = 0; i < 4; i++)
#pragma unroll
        for (int j = 0; j < 4; j++)
#pragma unroll
            for (int r = 0; r < 4; r++) c[i][j][r] = 0.0f;

    gemm_issue(A, W, row0, col0, 0, 0, sA, sB, arow, acol4, brow, bcol4);

    int stage = 0;
    for (int kb = 0; kb < HH / 32; kb++) {
        if (kb + 1 < HH / 32) {
            gemm_issue(A, W, row0, col0, kb + 1, stage ^ 1, sA, sB,
                       arow, acol4, brow, bcol4);
            cpwait<1>();
        } else {
            cpwait<0>();
        }
        __syncthreads();

        const float* as = As + stage * ASTAGE + (warp_m * 64) * ASTRIDE;
        const float* bs = Bs + stage * BSTAGE + warp_n * 32;

#pragma unroll
        for (int ks = 0; ks < 4; ks++) {
            const int k = ks * 8;
            uint32_t bhi[4][2], blo[4][2];
#pragma unroll
            for (int nj = 0; nj < 4; nj++) {
#pragma unroll
                for (int r = 0; r < 2; r++) {
                    float v = bs[(k + qid + r * 4) * BSTRIDE + nj * 8 + grp];
                    uint32_t hbits = f2tf32(v);
                    bhi[nj][r] = hbits;
                    blo[nj][r] = f2tf32(v - __uint_as_float(hbits));
                }
            }
#pragma unroll
            for (int mi = 0; mi < 4; mi++) {
                float ar[4];
                ar[0] = as[(mi * 16 + grp) * ASTRIDE + k + qid];
                ar[1] = as[(mi * 16 + grp + 8) * ASTRIDE + k + qid];
                ar[2] = as[(mi * 16 + grp) * ASTRIDE + k + qid + 4];
                ar[3] = as[(mi * 16 + grp + 8) * ASTRIDE + k + qid + 4];
                uint32_t ah[4];
                cvt4(ar, ah);
#pragma unroll
                for (int nj = 0; nj < 4; nj++) {
                    mma_tf32(c[mi][nj], ah, blo[nj]);
                    mma_tf32(c[mi][nj], ah, bhi[nj]);
                }
            }
        }
        __syncthreads();
        stage ^= 1;
    }

#pragma unroll
    for (int mi = 0; mi < 4; mi++) {
        int r0 = row0 + warp_m * 64 + mi * 16 + grp;
#pragma unroll
        for (int nj = 0; nj < 4; nj++) {
            int cc = col0 + warp_n * 32 + nj * 8 + 2 * qid;
            float v0 = c[mi][nj][0], v1 = c[mi][nj][1];
            float v2 = c[mi][nj][2], v3 = c[mi][nj][3];
            if (act) {
                v0 = gelu_tanh(v0); v1 = gelu_tanh(v1);
                v2 = gelu_tanh(v2); v3 = gelu_tanh(v3);
            }
            *(float2*)(C + (size_t)r0 * HH + cc) = make_float2(v0, v1);
            *(float2*)(C + (size_t)(r0 + 8) * HH + cc) = make_float2(v2, v3);
        }
    }
}

__global__ __launch_bounds__(256) void gemm_tc(
    const float* __restrict__ W,
    const float* __restrict__ Aext,
    float*       Cext,
    int srcsel, int dstsel, int act)
{
    const float* A = (srcsel == 0) ? Aext : g_tmp;
    float* C = (dstsel == 0) ? g_xqk :
               (dstsel == 1) ? g_xvraw :
               (dstsel == 2) ? g_gate : Cext;
    gemm_body(A, W, C, blockIdx.x, blockIdx.y, act);
}

// combined wq+wv gemm: grid (12, 64)
__global__ __launch_bounds__(256) void gemm_qv(
    const float* __restrict__ hs,
    const float* __restrict__ wq,
    const float* __restrict__ wv)
{
    int bx = blockIdx.x;
    if (bx < 6) gemm_body(hs, wq, g_xqk, bx, blockIdx.y, 0);
    else        gemm_body(hs, wv, g_xvraw, bx - 6, blockIdx.y, 0);
}

// ------- causal conv (K=4) + RoPE + permute + lr, 4 rows per block -------
__global__ __launch_bounds__(384) void convrope_kernel(
    const int*   __restrict__ pids,
    const float* __restrict__ cqk, const float* __restrict__ cqb,
    const float* __restrict__ ckk, const float* __restrict__ ckb,
    const float* __restrict__ hs,
    const float* __restrict__ lrw, const float* __restrict__ lrb)
{
    __shared__ float sxh[4][HH];
    int blk = blockIdx.x;
    int tid = threadIdx.x;
    int b = blk >> 9;
    int t0 = (blk & 511) * 4;
    int c = tid * 2;

#pragma unroll
    for (int r = 0; r < 4; r++) {
        size_t ro = (size_t)(b * NSEQ + t0 + r) * HH;
        sxh[r][tid]       = hs[ro + tid];
        sxh[r][tid + 384] = hs[ro + tid + 384];
    }

    float wq0[4], wq1[4], wk0[4], wk1[4];
#pragma unroll
    for (int j = 0; j < 4; j++) {
        wq0[j] = cqk[j * HH + c];
        wq1[j] = cqk[j * HH + c + 1];
        wk0[j] = ckk[j * HH + c];
        wk1[j] = ckk[j * HH + c + 1];
    }
    float bq0 = cqb[c], bq1 = cqb[c + 1];
    float bk0 = ckb[c], bk1 = ckb[c + 1];

    int h = c / 64;
    int d = c & 63;
    int f = d >> 1;
    float theta = expf(-(float)f * (9.210340371976184f / 32.0f));

#pragma unroll
    for (int r = 0; r < 4; r++) {
        int t = t0 + r;
        float q0 = bq0, q1 = bq1, k0 = bk0, k1 = bk1;
#pragma unroll
        for (int j = 0; j < 4; j++) {
            int src = t - 4 + j;
            if (src >= 0) {
                const float* xr = g_xqk + ((size_t)(b * NSEQ + src)) * HH + c;
                float x0 = xr[0], x1 = xr[1];
                q0 = fmaf(x0, wq0[j], q0);
                q1 = fmaf(x1, wq1[j], q1);
                k0 = fmaf(x0, wk0[j], k0);
                k1 = fmaf(x1, wk1[j], k1);
            }
        }

        int pid = pids[b * NSEQ + t];
        int rr = ((pid % MM) + MM) % MM;
        float ang = (float)rr * theta;
        float sn, cs;
        sincosf(ang, &sn, &cs);

        float xq0 = q0 * cs - q1 * sn, xq1 = q0 * sn + q1 * cs;
        float xk0 = k0 * cs - k1 * sn, xk1 = k0 * sn + k1 * cs;

        int n = t >> 4, m = t & 15;
        size_t o = ((((size_t)b * NHEAD + h) * NMB + n) * MM + m) * HDIM + d;
        g_xq[o] = xq0; g_xq[o + 1] = xq1;
        g_xk[o] = xk0; g_xk[o + 1] = xk1;
        size_t vi = (size_t)(b * NSEQ + t) * HH + c;
        g_xv[o]     = g_xvraw[vi];
        g_xv[o + 1] = g_xvraw[vi + 1];
    }

    __syncthreads();
    int w = tid >> 5, lane = tid & 31;
    const float* ww = lrw + (size_t)w * HH;
    float s0 = 0.0f, s1 = 0.0f, s2 = 0.0f, s3 = 0.0f;
#pragma unroll 6
    for (int dd = lane; dd < HH; dd += 32) {
        float wv = ww[dd];
        s0 = fmaf(sxh[0][dd], wv, s0);
        s1 = fmaf(sxh[1][dd], wv, s1);
        s2 = fmaf(sxh[2][dd], wv, s2);
        s3 = fmaf(sxh[3][dd], wv, s3);
    }
    wred4(s0, s1, s2, s3);
    if (lane == 0) {
        float lb = lrb[w];
#pragma unroll
        for (int r = 0; r < 4; r++) {
            float sv = (r == 0) ? s0 : (r == 1) ? s1 : (r == 2) ? s2 : s3;
            float v = 1.0f / (1.0f + expf(-(sv + lb)));
            int t = t0 + r;
            int n = t >> 4, m = t & 15;
            g_lr[(((size_t)b * NHEAD + w) * NMB + n) * MM + m] = v;
        }
    }
}

// ================== tensor-core TTT scan (3-sync, ldmatrix A) =============
#define SWST 66
#define SGST 66
#define STS2 68
#define TILEF (16 * STS2)
#define STAGEF (3 * TILEF)

__device__ __forceinline__ void scan_prefetch(
    const float* pk, const float* pq, const float* pv, const float* plr,
    int n, int st, uint32_t stile_u, uint32_t slr_u, int tid)
{
    int row = tid >> 4, col = (tid & 15) * 4;
    int gi = n * 1024 + row * 64 + col;
    uint32_t dst = stile_u + (uint32_t)(st * STAGEF + row * STS2 + col) * 4u;
    CPA16(dst,                 pk + gi);
    CPA16(dst + TILEF * 4,     pq + gi);
    CPA16(dst + 2 * TILEF * 4, pv + gi);
    if (tid < 4) CPA16(slr_u + (uint32_t)(st * 16 + tid * 4) * 4u,
                       plr + n * 16 + tid * 4);
    CPCOMMIT();
}

__device__ void scan_body_tc(int bh,
    const float* __restrict__ W1_0, const float* __restrict__ b1_0,
    const float* __restrict__ gamma, const float* __restrict__ beta,
    const float* __restrict__ lti)
{
    extern __shared__ float sm[];
    float*  sWp   = sm;                        // [64][66]
    float*  sgl   = sWp + 64 * SWST;           // [16][66]
    float*  stile = sgl + 16 * SGST;           // 2 stages x (xk,xq,xv)
    float*  slr2  = stile + 2 * STAGEF;        // [2][16]
    float*  szk   = slr2 + 32;                 // [16][68] zk transpose
    float*  sb1   = szk + 16 * STS2;           // [64]

    int h = bh % NHEAD;
    int tid = threadIdx.x;
    int w = tid >> 5, lane = tid & 31;
    int grp = lane >> 2, qid = lane & 3;
    int col0 = 8 * w + 2 * qid;
    int m0 = 2 * w, m1 = 2 * w + 1;
    int e = 2 * lane;

    float wacc[4][4];
#pragma unroll
    for (int mt = 0; mt < 4; mt++) {
        float2 v0 = *(const float2*)&W1_0[(size_t)h * 4096 + (16 * mt + grp) * 64 + col0];
        float2 v1 = *(const float2*)&W1_0[(size_t)h * 4096 + (16 * mt + grp + 8) * 64 + col0];
        wacc[mt][0] = v0.x; wacc[mt][1] = v0.y;
        wacc[mt][2] = v1.x; wacc[mt][3] = v1.y;
    }
    if (tid < 64) sb1[tid] = b1_0[h * 64 + tid];
    float gR0 = gamma[h * 64 + e], gR1 = gamma[h * 64 + e + 1];
    float btR0 = beta[h * 64 + e], btR1 = beta[h * 64 + e + 1];
    float ls = fmaxf(lti[15] + (1.0f / 16.0f), 0.0f) * (1.0f / 64.0f);

    const float* pk = g_xk + (size_t)bh * NMB * 1024;
    const float* pq = g_xq + (size_t)bh * NMB * 1024;
    const float* pv = g_xv + (size_t)bh * NMB * 1024;
    const float* plr = g_lr + (size_t)bh * NMB * 16;
    uint32_t stile_u = (uint32_t)__cvta_generic_to_shared(stile);
    uint32_t slr_u   = (uint32_t)__cvta_generic_to_shared(slr2);

    uint32_t aoff = (uint32_t)((lane & 15) * STS2 + (lane >> 4) * 4) * 4u;

    scan_prefetch(pk, pq, pv, plr, 0, 0, stile_u, slr_u, tid);

    for (int n = 0; n < NMB; n++) {
        int st = n & 1;
#pragma unroll
        for (int mt = 0; mt < 4; mt++) {
            *(float2*)&sWp[(16 * mt + grp) * SWST + col0] =
                make_float2(wacc[mt][0], wacc[mt][1]);
            *(float2*)&sWp[(16 * mt + grp + 8) * SWST + col0] =
                make_float2(wacc[mt][2], wacc[mt][3]);
        }
        cpwait<0>();
        __syncthreads();                                   // sync1
        if (n + 1 < NMB)
            scan_prefetch(pk, pq, pv, plr, n + 1, st ^ 1, stile_u, slr_u, tid);

        float* sxk = stile + st * STAGEF;
        float* sxv = sxk + 2 * TILEF;
        uint32_t sxk_u = stile_u + (uint32_t)(st * STAGEF) * 4u;
        uint32_t sxq_u = sxk_u + TILEF * 4u;

        // ---- Z1 = xk@W, Zq = xq@W (A via ldmatrix.x4) ----
        float zkh[4] = {0, 0, 0, 0}, zkl[4] = {0, 0, 0, 0};
        float zqh[4] = {0, 0, 0, 0}, zql[4] = {0, 0, 0, 0};
#pragma unroll
        for (int kt = 0; kt < 8; kt++) {
            int k = 8 * kt;
            float b0r = sWp[(k + qid) * SWST + 8 * w + grp];
            float b1r = sWp[(k + qid + 4) * SWST + 8 * w + grp];
            uint32_t bhi[2], blo[2];
            bhi[0] = f2tf32(b0r); blo[0] = f2tf32(b0r - __uint_as_float(bhi[0]));
            bhi[1] = f2tf32(b1r); blo[1] = f2tf32(b1r - __uint_as_float(bhi[1]));
            uint32_t araw[4], ah[4];
            LDMX4(araw, sxk_u + aoff + k * 4);
#pragma unroll
            for (int i = 0; i < 4; i++) ah[i] = f2tf32(__uint_as_float(araw[i]));
            mma_tf32(zkl, ah, blo); mma_tf32(zkh, ah, bhi);
            LDMX4(araw, sxq_u + aoff + k * 4);
#pragma unroll
            for (int i = 0; i < 4; i++) ah[i] = f2tf32(__uint_as_float(araw[i]));
            mma_tf32(zql, ah, blo); mma_tf32(zqh, ah, bhi);
        }
        float bb0 = sb1[col0], bb1 = sb1[col0 + 1];
        float zk0 = zkh[0] + zkl[0] + bb0, zk1 = zkh[1] + zkl[1] + bb1;
        float zk2 = zkh[2] + zkl[2] + bb0, zk3 = zkh[3] + zkl[3] + bb1;
        float zq0 = zqh[0] + zql[0] + bb0, zq1 = zqh[1] + zql[1] + bb1;
        float zq2 = zqh[2] + zql[2] + bb0, zq3 = zqh[3] + zql[3] + bb1;

        size_t base = ((size_t)bh * NMB + n) * 1024;
        *(float2*)&g_zq[base + grp * 64 + col0]       = make_float2(zq0, zq1);
        *(float2*)&g_zq[base + (grp + 8) * 64 + col0] = make_float2(zq2, zq3);

        *(float2*)&szk[grp * STS2 + col0]       = make_float2(zk0, zk1);
        *(float2*)&szk[(grp + 8) * STS2 + col0] = make_float2(zk2, zk3);
        __syncthreads();                                   // sync2

        // ---- warp-local LN-L2 backward: warp w owns rows m0, m1 ----
        float2 za = *(const float2*)&szk[m0 * STS2 + e];
        float2 zb = *(const float2*)&szk[m1 * STS2 + e];
        float s1a = za.x + za.y, s2a = za.x * za.x + za.y * za.y;
        float s1b = zb.x + zb.y, s2b = zb.x * zb.x + zb.y * zb.y;
        wred4(s1a, s2a, s1b, s2b);
        float mu0 = s1a * (1.0f / 64.0f);
        float rs0 = rsqrtf(s2a * (1.0f / 64.0f) - mu0 * mu0 + 1e-5f);
        float mu1 = s1b * (1.0f / 64.0f);
        float rs1 = rsqrtf(s2b * (1.0f / 64.0f) - mu1 * mu1 + 1e-5f);
        float xh00 = (za.x - mu0) * rs0, xh01 = (za.y - mu0) * rs0;
        float xh10 = (zb.x - mu1) * rs1, xh11 = (zb.y - mu1) * rs1;
        float2 xv0 = *(const float2*)&sxv[m0 * STS2 + e];
        float2 xv1 = *(const float2*)&sxv[m1 * STS2 + e];
        float2 xk0v = *(const float2*)&sxk[m0 * STS2 + e];
        float2 xk1v = *(const float2*)&sxk[m1 * STS2 + e];
        float gy00 = (fmaf(gR0, xh00, btR0) - (xv0.x - xk0v.x)) * gR0;
        float gy01 = (fmaf(gR1, xh01, btR1) - (xv0.y - xk0v.y)) * gR1;
        float gy10 = (fmaf(gR0, xh10, btR0) - (xv1.x - xk1v.x)) * gR0;
        float gy11 = (fmaf(gR1, xh11, btR1) - (xv1.y - xk1v.y)) * gR1;
        float t1a = gy00 + gy01, t2a = gy00 * xh00 + gy01 * xh01;
        float t1b = gy10 + gy11, t2b = gy10 * xh10 + gy11 * xh11;
        wred4(t1a, t2a, t1b, t2b);
        float sc0 = rs0 * (1.0f / 64.0f), sc1 = rs1 * (1.0f / 64.0f);
        float gr00 = (64.0f * gy00 - t1a - xh00 * t2a) * sc0;
        float gr01 = (64.0f * gy01 - t1a - xh01 * t2a) * sc0;
        float gr10 = (64.0f * gy10 - t1b - xh10 * t2b) * sc1;
        float gr11 = (64.0f * gy11 - t1b - xh11 * t2b) * sc1;

        *(float2*)&g_grad[base + m0 * 64 + e] = make_float2(gr00, gr01);
        *(float2*)&g_grad[base + m1 * 64 + e] = make_float2(gr10, gr11);

        float lr0 = ls * slr2[st * 16 + m0];
        float lr1 = ls * slr2[st * 16 + m1];
        *(float2*)&sgl[m0 * SGST + e] = make_float2(-lr0 * gr00, -lr0 * gr01);
        *(float2*)&sgl[m1 * SGST + e] = make_float2(-lr1 * gr10, -lr1 * gr11);
        __syncthreads();                                   // sync3

        // ---- W += xk^T @ sgl ----
#pragma unroll
        for (int kt = 0; kt < 2; kt++) {
            int k = 8 * kt;
            float b0r = sgl[(k + qid) * SGST + 8 * w + grp];
            float b1r = sgl[(k + qid + 4) * SGST + 8 * w + grp];
            uint32_t bhi[2], blo[2];
            bhi[0] = f2tf32(b0r); blo[0] = f2tf32(b0r - __uint_as_float(bhi[0]));
            bhi[1] = f2tf32(b1r); blo[1] = f2tf32(b1r - __uint_as_float(bhi[1]));
#pragma unroll
            for (int mt = 0; mt < 4; mt++) {
                float ar[4];
                uint32_t ah[4];
                ar[0] = sxk[(k + qid) * STS2 + 16 * mt + grp];
                ar[1] = sxk[(k + qid) * STS2 + 16 * mt + grp + 8];
                ar[2] = sxk[(k + qid + 4) * STS2 + 16 * mt + grp];
                ar[3] = sxk[(k + qid + 4) * STS2 + 16 * mt + grp + 8];
                cvt4(ar, ah);
                mma_tf32(wacc[mt], ah, blo);
                mma_tf32(wacc[mt], ah, bhi);
            }
        }
        if (tid < 64) {
            float s = 0.0f;
#pragma unroll
            for (int mm2 = 0; mm2 < 16; mm2++) s += sgl[mm2 * SGST + tid];
            sb1[tid] += s;
        }
    }
}

// ---------------- fused: 148 CTAs = 48 scan (dedicated SMs) + 100 gemm ----
__global__ __launch_bounds__(256) void fused_scan_gate(
    const float* __restrict__ hs, const float* __restrict__ wg,
    const float* __restrict__ W1_0, const float* __restrict__ b1_0,
    const float* __restrict__ gamma, const float* __restrict__ beta,
    const float* __restrict__ lti)
{
    if (blockIdx.x < NCHAIN) {
        scan_body_tc(blockIdx.x, W1_0, b1_0, gamma, beta, lti);
    } else {
        for (int t = blockIdx.x - NCHAIN; t < 384; t += 100)
            gemm_body(hs, wg, g_gate, t % 6, t / 6, 1);
    }
}

// ---------------- parallel epilogue: y = xq + LN(Zq - coef@grad) ----------
__global__ __launch_bounds__(256) void epilogue_y(
    const float* __restrict__ gamma, const float* __restrict__ beta,
    const float* __restrict__ lti)
{
    int blk = blockIdx.x;
    int bh = blk >> 7;
    int n  = blk & 127;
    int b = bh / NHEAD, h = bh % NHEAD;

    __shared__ float sxq[16 * STS2], sxk[16 * STS2], sgr[16 * STS2];
    __shared__ float szq[16 * 64];
    __shared__ float scoef[256], stok[16], slr[16], sg[64], sbt[64];

    int tid = threadIdx.x;
    int row = tid >> 4, col = (tid & 15) * 4;
    size_t base = ((size_t)bh * NMB + n) * 1024;
    int gi = row * 64 + col;
    *(float4*)&sxq[row * STS2 + col] =
        *(const float4*)&g_xq[(size_t)bh * NMB * 1024 + n * 1024 + gi];
    *(float4*)&sxk[row * STS2 + col] =
        *(const float4*)&g_xk[(size_t)bh * NMB * 1024 + n * 1024 + gi];
    *(float4*)&sgr[row * STS2 + col] = *(const float4*)&g_grad[base + gi];
    *(float4*)&szq[gi]               = *(const float4*)&g_zq[base + gi];
    if (tid < 16) {
        stok[tid] = fmaxf(lti[tid] + 1.0f / (float)(tid + 1), 0.0f);
        slr[tid]  = g_lr[(size_t)bh * NMB * 16 + n * 16 + tid];
    }
    if (tid < 64) {
        sg[tid]  = gamma[h * 64 + tid];
        sbt[tid] = beta[h * 64 + tid];
    }
    __syncthreads();

    {
        int mm = tid >> 4, nn = tid & 15;
        float a = 0.0f;
#pragma unroll
        for (int d = 0; d < 64; d += 4) {
            float4 qv = *(const float4*)&sxq[mm * STS2 + d];
            float4 kv = *(const float4*)&sxk[nn * STS2 + d];
            a = fmaf(qv.x, kv.x, a);
            a = fmaf(qv.y, kv.y, a);
            a = fmaf(qv.z, kv.z, a);
            a = fmaf(qv.w, kv.w, a);
        }
        scoef[tid] = (nn <= mm)
            ? stok[mm] * slr[nn] * (1.0f / 64.0f) * (a + 1.0f)
            : 0.0f;
    }
    __syncthreads();

    int w = tid >> 5, lane = tid & 31;
    int m0 = 2 * w, m1 = 2 * w + 1;
    int e = 2 * lane;
    float2 z0 = *(const float2*)&szq[m0 * 64 + e];
    float2 z1 = *(const float2*)&szq[m1 * 64 + e];
    float zq00 = z0.x, zq01 = z0.y, zq10 = z1.x, zq11 = z1.y;
#pragma unroll
    for (int nn = 0; nn < 16; nn++) {
        float c0 = scoef[m0 * 16 + nn];
        float c1 = scoef[m1 * 16 + nn];
        float2 gv = *(const float2*)&sgr[nn * STS2 + e];
        zq00 = fmaf(-c0, gv.x, zq00); zq01 = fmaf(-c0, gv.y, zq01);
        zq10 = fmaf(-c1, gv.x, zq10); zq11 = fmaf(-c1, gv.y, zq11);
    }
    float s1a = zq00 + zq01, s2a = zq00 * zq00 + zq01 * zq01;
    float s1b = zq10 + zq11, s2b = zq10 * zq10 + zq11 * zq11;
    wred4(s1a, s2a, s1b, s2b);
    float mu0 = s1a * (1.0f / 64.0f);
    float rs0 = rsqrtf(s2a * (1.0f / 64.0f) - mu0 * mu0 + 1e-5f);
    float mu1 = s1b * (1.0f / 64.0f);
    float rs1 = rsqrtf(s2b * (1.0f / 64.0f) - mu1 * mu1 + 1e-5f);
    float g0 = sg[e], g1 = sg[e + 1], bt0 = sbt[e], bt1 = sbt[e + 1];
    float2 qx0 = *(const float2*)&sxq[m0 * STS2 + e];
    float2 qx1 = *(const float2*)&sxq[m1 * STS2 + e];
    float y00 = qx0.x + fmaf((zq00 - mu0) * rs0, g0, bt0);
    float y01 = qx0.y + fmaf((zq01 - mu0) * rs0, g1, bt1);
    float y10 = qx1.x + fmaf((zq10 - mu1) * rs1, g0, bt0);
    float y11 = qx1.y + fmaf((zq11 - mu1) * rs1, g1, bt1);
    size_t or0 = ((size_t)(b * NSEQ + n * MM + m0)) * HH + h * HDIM + e;
    size_t or1 = ((size_t)(b * NSEQ + n * MM + m1)) * HH + h * HDIM + e;
    *(float2*)&g_y[or0] = make_float2(y00, y01);
    *(float2*)&g_y[or1] = make_float2(y10, y11);
}

// ------- post-norm + gate multiply, 192 threads, float4 I/O --------------
__global__ __launch_bounds__(192) void postnorm_kernel(
    const float* __restrict__ pns, const float* __restrict__ pnb)
{
    int row = blockIdx.x;
    int tid = threadIdx.x;
    const float* y = g_y + (size_t)row * HH;
    float4 v = *(const float4*)(y + tid * 4);
    float s1 = v.x + v.y + v.z + v.w;
    float s2 = v.x * v.x + v.y * v.y + v.z * v.z + v.w * v.w;
    wred2(s1, s2);
    __shared__ float r1[6], r2[6];
    int wid = tid >> 5, ln = tid & 31;
    if (ln == 0) { r1[wid] = s1; r2[wid] = s2; }
    __syncthreads();
    float a = 0.0f, bsum = 0.0f;
#pragma unroll
    for (int i = 0; i < 6; i++) { a += r1[i]; bsum += r2[i]; }
    float mu = a * (1.0f / 768.0f);
    float rstd = rsqrtf(bsum * (1.0f / 768.0f) - mu * mu + 1e-5f);
    float4 sc = *(const float4*)(pns + tid * 4);
    float4 bi = *(const float4*)(pnb + tid * 4);
    float4 gt = *(const float4*)(g_gate + (size_t)row * HH + tid * 4);
    float4 o;
    o.x = gt.x * fmaf((v.x - mu) * rstd, sc.x, bi.x);
    o.y = gt.y * fmaf((v.y - mu) * rstd, sc.y, bi.y);
    o.z = gt.z * fmaf((v.z - mu) * rstd, sc.z, bi.z);
    o.w = gt.w * fmaf((v.w - mu) * rstd, sc.w, bi.w);
    *(float4*)(g_tmp + (size_t)row * HH + tid * 4) = o;
}

// ---------------- launch --------------------------------------------------
extern "C" void kernel_launch(void* const* d_in, const int* in_sizes, int n_in,
                              void* d_out, int out_size)
{
    const float* hs  = (const float*)d_in[0];
    const int*   pid = (const int*)  d_in[1];
    const float* wq  = (const float*)d_in[2];
    const float* wv  = (const float*)d_in[3];
    const float* wo  = (const float*)d_in[4];
    const float* wg  = (const float*)d_in[5];
    const float* cqk = (const float*)d_in[6];
    const float* cqb = (const float*)d_in[7];
    const float* ckk = (const float*)d_in[8];
    const float* ckb = (const float*)d_in[9];
    const float* lrw = (const float*)d_in[10];
    const float* lrb = (const float*)d_in[11];
    const float* lti = (const float*)d_in[12];
    const float* gam = (const float*)d_in[13];
    const float* bet = (const float*)d_in[14];
    const float* pns = (const float*)d_in[15];
    const float* pnb = (const float*)d_in[16];
    const float* W10 = (const float*)d_in[17];
    const float* b10 = (const float*)d_in[18];
    float* out = (float*)d_out;

    cudaFuncSetAttribute(gemm_tc, cudaFuncAttributeMaxDynamicSharedMemorySize,
                         GEMM_SMEM);
    cudaFuncSetAttribute(gemm_qv, cudaFuncAttributeMaxDynamicSharedMemorySize,
                         GEMM_SMEM);
    cudaFuncSetAttribute(fused_scan_gate,
                         cudaFuncAttributeMaxDynamicSharedMemorySize, GEMM_SMEM);

    dim3 qvgrid(12, BNROWS / 128);       // wq + wv combined
    dim3 ggrid(HH / 128, BNROWS / 128);  // (6, 64)

    gemm_qv<<<qvgrid, 256, GEMM_SMEM>>>(hs, wq, wv);

    convrope_kernel<<<BNROWS / 4, 384>>>(pid, cqk, cqb, ckk, ckb, hs, lrw, lrb);

    fused_scan_gate<<<148, 256, GEMM_SMEM>>>(hs, wg, W10, b10, gam, bet, lti);

    epilogue_y<<<NCHAIN * NMB, 256>>>(gam, bet, lti);

    postnorm_kernel<<<BNROWS, 192>>>(pns, pnb);

    gemm_tc<<<ggrid, 256, GEMM_SMEM>>>(wo, nullptr, out, 1, 3, 0);  // final
}

// round 16
// speedup vs baseline: 1.1148x; 1.0036x over previous
#include <cuda_runtime.h>
#include <cstdint>

#define BB 4
#define NSEQ 2048
#define HH 768
#define NHEAD 12
#define HDIM 64
#define MM 16
#define NMB 128            // NSEQ / MM
#define BNROWS 8192        // BB * NSEQ
#define NCHAIN (BB * NHEAD)

// ---------------- scratch (static device globals: allocation-free) -------
__device__ float g_xqk  [BNROWS * HH];
__device__ float g_xvraw[BNROWS * HH];
__device__ float g_gate [BNROWS * HH];
__device__ float g_xq   [BNROWS * HH];   // [B][NH][NMB][M][HD]
__device__ float g_xk   [BNROWS * HH];
__device__ float g_xv   [BNROWS * HH];
__device__ float g_y    [BNROWS * HH];   // [B*N][768]
__device__ float g_tmp  [BNROWS * HH];
__device__ float g_lr   [NCHAIN * NMB * MM];
__device__ float g_zq   [NCHAIN * NMB * MM * HDIM];
__device__ float g_grad [NCHAIN * NMB * MM * HDIM];

__device__ __forceinline__ float gelu_tanh(float x) {
    const float c0 = 0.7978845608028654f;   // sqrt(2/pi)
    float x3 = x * x * x;
    return 0.5f * x * (1.0f + tanhf(c0 * (x + 0.044715f * x3)));
}

__device__ __forceinline__ void wred2(float& a, float& b) {
#pragma unroll
    for (int o = 16; o; o >>= 1) {
        a += __shfl_xor_sync(0xffffffffu, a, o);
        b += __shfl_xor_sync(0xffffffffu, b, o);
    }
}

__device__ __forceinline__ void wred4(float& a, float& b, float& c, float& d) {
#pragma unroll
    for (int o = 16; o; o >>= 1) {
        a += __shfl_xor_sync(0xffffffffu, a, o);
        b += __shfl_xor_sync(0xffffffffu, b, o);
        c += __shfl_xor_sync(0xffffffffu, c, o);
        d += __shfl_xor_sync(0xffffffffu, d, o);
    }
}

// ================== tf32 mma helpers ======================================
__device__ __forceinline__ uint32_t f2tf32(float x) {
    uint32_t r;
    asm("cvt.rna.tf32.f32 %0, %1;" : "=r"(r) : "f"(x));
    return r;
}

__device__ __forceinline__ void mma_tf32(float c[4], const uint32_t a[4],
                                         const uint32_t b[2]) {
    asm volatile(
        "mma.sync.aligned.m16n8k8.row.col.f32.tf32.tf32.f32 "
        "{%0,%1,%2,%3},{%4,%5,%6,%7},{%8,%9},{%0,%1,%2,%3};"
        : "+f"(c[0]), "+f"(c[1]), "+f"(c[2]), "+f"(c[3])
        : "r"(a[0]), "r"(a[1]), "r"(a[2]), "r"(a[3]), "r"(b[0]), "r"(b[1]));
}

__device__ __forceinline__ void cvt4(const float ar[4], uint32_t a[4]) {
#pragma unroll
    for (int i = 0; i < 4; i++) a[i] = f2tf32(ar[i]);
}

#define LDMX4(r, addr) \
    asm volatile("ldmatrix.sync.aligned.m8n8.x4.shared.b16 {%0,%1,%2,%3}, [%4];" \
        : "=r"((r)[0]), "=r"((r)[1]), "=r"((r)[2]), "=r"((r)[3]) : "r"(addr))

#define CPA16(dst, src) \
    asm volatile("cp.async.cg.shared.global [%0], [%1], 16;" :: "r"(dst), "l"(src))
#define CPCOMMIT() asm volatile("cp.async.commit_group;")
template <int N>
__device__ __forceinline__ void cpwait() {
    asm volatile("cp.async.wait_group %0;" :: "n"(N));
}

// ================== big GEMM (128x128x32, A=tf32, B=hi/lo tf32) ==========
#define ASTRIDE 36
#define BSTRIDE 136
#define ASTAGE  (128 * ASTRIDE)
#define BSTAGE  (32 * BSTRIDE)
#define GEMM_SMEM ((2 * ASTAGE + 2 * BSTAGE) * 4)   // 71680 bytes

__device__ __forceinline__ void gemm_issue(
    const float* A, const float* W, int row0, int col0, int kb, int stage,
    uint32_t sA, uint32_t sB, int arow, int acol4, int brow, int bcol4)
{
    const float* ag = A + (size_t)(row0 + arow) * HH + kb * 32 + acol4;
    uint32_t ad = sA + (uint32_t)(stage * ASTAGE + arow * ASTRIDE + acol4) * 4u;
#pragma unroll
    for (int p = 0; p < 4; p++)
        CPA16(ad + p * 32 * ASTRIDE * 4, ag + (size_t)p * 32 * HH);
    const float* bg = W + (size_t)(kb * 32 + brow) * HH + col0 + bcol4;
    uint32_t bd = sB + (uint32_t)(stage * BSTAGE + brow * BSTRIDE + bcol4) * 4u;
#pragma unroll
    for (int p = 0; p < 4; p++)
        CPA16(bd + p * 8 * BSTRIDE * 4, bg + (size_t)p * 8 * HH);
    CPCOMMIT();
}

__device__ void gemm_body(const float* __restrict__ A,
                          const float* __restrict__ W,
                          float* __restrict__ C,
                          int bx, int by, int act)
{
    extern __shared__ float smem[];
    float* As = smem;
    float* Bs = smem + 2 * ASTAGE;

    int tid = threadIdx.x;
    int wid = tid >> 5, lane = tid & 31;
    int warp_m = wid & 1, warp_n = wid >> 1;
    int grp = lane >> 2, qid = lane & 3;
    int row0 = by * 128, col0 = bx * 128;

    int arow = tid >> 3, acol4 = (tid & 7) * 4;
    int brow = tid >> 5, bcol4 = (tid & 31) * 4;

    uint32_t sA = (uint32_t)__cvta_generic_to_shared(As);
    uint32_t sB = (uint32_t)__cvta_generic_to_shared(Bs);

    float c[4][4][4];
#pragma unroll
    for (int i = 0; i < 4; i++)
#pragma unroll
        for (int j = 0; j < 4; j++)
#pragma unroll
            for (int r = 0; r < 4; r++) c[i][j][r] = 0.0f;

    gemm_issue(A, W, row0, col0, 0, 0, sA, sB, arow, acol4, brow, bcol4);

    int stage = 0;
    for (int kb = 0; kb < HH / 32; kb++) {
        if (kb + 1 < HH / 32) {
            gemm_issue(A, W, row0, col0, kb + 1, stage ^ 1, sA, sB,
                       arow, acol4, brow, bcol4);
            cpwait<1>();
        } else {
            cpwait<0>();
        }
        __syncthreads();

        const float* as = As + stage * ASTAGE + (warp_m * 64) * ASTRIDE;
        const float* bs = Bs + stage * BSTAGE + warp_n * 32;

#pragma unroll
        for (int ks = 0; ks < 4; ks++) {
            const int k = ks * 8;
            uint32_t bhi[4][2], blo[4][2];
#pragma unroll
            for (int nj = 0; nj < 4; nj++) {
#pragma unroll
                for (int r = 0; r < 2; r++) {
                    float v = bs[(k + qid + r * 4) * BSTRIDE + nj * 8 + grp];
                    uint32_t hbits = f2tf32(v);
                    bhi[nj][r] = hbits;
                    blo[nj][r] = f2tf32(v - __uint_as_float(hbits));
                }
            }
#pragma unroll
            for (int mi = 0; mi < 4; mi++) {
                float ar[4];
                ar[0] = as[(mi * 16 + grp) * ASTRIDE + k + qid];
                ar[1] = as[(mi * 16 + grp + 8) * ASTRIDE + k + qid];
                ar[2] = as[(mi * 16 + grp) * ASTRIDE + k + qid + 4];
                ar[3] = as[(mi * 16 + grp + 8) * ASTRIDE + k + qid + 4];
                uint32_t ah[4];
                cvt4(ar, ah);
#pragma unroll
                for (int nj = 0; nj < 4; nj++) {
                    mma_tf32(c[mi][nj], ah, blo[nj]);
                    mma_tf32(c[mi][nj], ah, bhi[nj]);
                }
            }
        }
        __syncthreads();
        stage ^= 1;
    }

#pragma unroll
    for (int mi = 0; mi < 4; mi++) {
        int r0 = row0 + warp_m * 64 + mi * 16 + grp;
#pragma unroll
        for (int nj = 0; nj < 4; nj++) {
            int cc = col0 + warp_n * 32 + nj * 8 + 2 * qid;
            float v0 = c[mi][nj][0], v1 = c[mi][nj][1];
            float v2 = c[mi][nj][2], v3 = c[mi][nj][3];
            if (act) {
                v0 = gelu_tanh(v0); v1 = gelu_tanh(v1);
                v2 = gelu_tanh(v2); v3 = gelu_tanh(v3);
            }
            *(float2*)(C + (size_t)r0 * HH + cc) = make_float2(v0, v1);
            *(float2*)(C + (size_t)(r0 + 8) * HH + cc) = make_float2(v2, v3);
        }
    }
}

__global__ __launch_bounds__(256) void gemm_tc(
    const float* __restrict__ W,
    const float* __restrict__ Aext,
    float*       Cext,
    int srcsel, int dstsel, int act)
{
    const float* A = (srcsel == 0) ? Aext : g_tmp;
    float* C = (dstsel == 0) ? g_xqk :
               (dstsel == 1) ? g_xvraw :
               (dstsel == 2) ? g_gate : Cext;
    gemm_body(A, W, C, blockIdx.x, blockIdx.y, act);
}

// combined wq+wv gemm: grid (12, 64)
__global__ __launch_bounds__(256) void gemm_qv(
    const float* __restrict__ hs,
    const float* __restrict__ wq,
    const float* __restrict__ wv)
{
    int bx = blockIdx.x;
    if (bx < 6) gemm_body(hs, wq, g_xqk, bx, blockIdx.y, 0);
    else        gemm_body(hs, wv, g_xvraw, bx - 6, blockIdx.y, 0);
}

// ------- causal conv (K=4) + RoPE + permute + lr, 4 rows per block -------
__global__ __launch_bounds__(384) void convrope_kernel(
    const int*   __restrict__ pids,
    const float* __restrict__ cqk, const float* __restrict__ cqb,
    const float* __restrict__ ckk, const float* __restrict__ ckb,
    const float* __restrict__ hs,
    const float* __restrict__ lrw, const float* __restrict__ lrb)
{
    __shared__ float sxh[4][HH];
    int blk = blockIdx.x;
    int tid = threadIdx.x;
    int b = blk >> 9;
    int t0 = (blk & 511) * 4;
    int c = tid * 2;

#pragma unroll
    for (int r = 0; r < 4; r++) {
        size_t ro = (size_t)(b * NSEQ + t0 + r) * HH;
        sxh[r][tid]       = hs[ro + tid];
        sxh[r][tid + 384] = hs[ro + tid + 384];
    }

    float wq0[4], wq1[4], wk0[4], wk1[4];
#pragma unroll
    for (int j = 0; j < 4; j++) {
        wq0[j] = cqk[j * HH + c];
        wq1[j] = cqk[j * HH + c + 1];
        wk0[j] = ckk[j * HH + c];
        wk1[j] = ckk[j * HH + c + 1];
    }
    float bq0 = cqb[c], bq1 = cqb[c + 1];
    float bk0 = ckb[c], bk1 = ckb[c + 1];

    int h = c / 64;
    int d = c & 63;
    int f = d >> 1;
    float theta = expf(-(float)f * (9.210340371976184f / 32.0f));

#pragma unroll
    for (int r = 0; r < 4; r++) {
        int t = t0 + r;
        float q0 = bq0, q1 = bq1, k0 = bk0, k1 = bk1;
#pragma unroll
        for (int j = 0; j < 4; j++) {
            int src = t - 4 + j;
            if (src >= 0) {
                const float* xr = g_xqk + ((size_t)(b * NSEQ + src)) * HH + c;
                float x0 = xr[0], x1 = xr[1];
                q0 = fmaf(x0, wq0[j], q0);
                q1 = fmaf(x1, wq1[j], q1);
                k0 = fmaf(x0, wk0[j], k0);
                k1 = fmaf(x1, wk1[j], k1);
            }
        }

        int pid = pids[b * NSEQ + t];
        int rr = ((pid % MM) + MM) % MM;
        float ang = (float)rr * theta;
        float sn, cs;
        sincosf(ang, &sn, &cs);

        float xq0 = q0 * cs - q1 * sn, xq1 = q0 * sn + q1 * cs;
        float xk0 = k0 * cs - k1 * sn, xk1 = k0 * sn + k1 * cs;

        int n = t >> 4, m = t & 15;
        size_t o = ((((size_t)b * NHEAD + h) * NMB + n) * MM + m) * HDIM + d;
        g_xq[o] = xq0; g_xq[o + 1] = xq1;
        g_xk[o] = xk0; g_xk[o + 1] = xk1;
        size_t vi = (size_t)(b * NSEQ + t) * HH + c;
        g_xv[o]     = g_xvraw[vi];
        g_xv[o + 1] = g_xvraw[vi + 1];
    }

    __syncthreads();
    int w = tid >> 5, lane = tid & 31;
    const float* ww = lrw + (size_t)w * HH;
    float s0 = 0.0f, s1 = 0.0f, s2 = 0.0f, s3 = 0.0f;
#pragma unroll 6
    for (int dd = lane; dd < HH; dd += 32) {
        float wv = ww[dd];
        s0 = fmaf(sxh[0][dd], wv, s0);
        s1 = fmaf(sxh[1][dd], wv, s1);
        s2 = fmaf(sxh[2][dd], wv, s2);
        s3 = fmaf(sxh[3][dd], wv, s3);
    }
    wred4(s0, s1, s2, s3);
    if (lane == 0) {
        float lb = lrb[w];
#pragma unroll
        for (int r = 0; r < 4; r++) {
            float sv = (r == 0) ? s0 : (r == 1) ? s1 : (r == 2) ? s2 : s3;
            float v = 1.0f / (1.0f + expf(-(sv + lb)));
            int t = t0 + r;
            int n = t >> 4, m = t & 15;
            g_lr[(((size_t)b * NHEAD + w) * NMB + n) * MM + m] = v;
        }
    }
}

// ================== tensor-core TTT scan (3-sync, ldmatrix A) =============
#define SWST 66
#define SGST 66
#define STS2 68
#define TILEF (16 * STS2)
#define STAGEF (3 * TILEF)

__device__ __forceinline__ void scan_prefetch(
    const float* pk, const float* pq, const float* pv, const float* plr,
    int n, int st, uint32_t stile_u, uint32_t slr_u, int tid)
{
    int row = tid >> 4, col = (tid & 15) * 4;
    int gi = n * 1024 + row * 64 + col;
    uint32_t dst = stile_u + (uint32_t)(st * STAGEF + row * STS2 + col) * 4u;
    CPA16(dst,                 pk + gi);
    CPA16(dst + TILEF * 4,     pq + gi);
    CPA16(dst + 2 * TILEF * 4, pv + gi);
    if (tid < 4) CPA16(slr_u + (uint32_t)(st * 16 + tid * 4) * 4u,
                       plr + n * 16 + tid * 4);
    CPCOMMIT();
}

__device__ void scan_body_tc(int bh,
    const float* __restrict__ W1_0, const float* __restrict__ b1_0,
    const float* __restrict__ gamma, const float* __restrict__ beta,
    const float* __restrict__ lti)
{
    extern __shared__ float sm[];
    float*  sWp   = sm;                        // [64][66]
    float*  sgl   = sWp + 64 * SWST;           // [16][66]
    float*  stile = sgl + 16 * SGST;           // 2 stages x (xk,xq,xv)
    float*  slr2  = stile + 2 * STAGEF;        // [2][16]
    float*  szk   = slr2 + 32;                 // [16][68] zk transpose
    float*  sb1   = szk + 16 * STS2;           // [64]

    int h = bh % NHEAD;
    int tid = threadIdx.x;
    int w = tid >> 5, lane = tid & 31;
    int grp = lane >> 2, qid = lane & 3;
    int col0 = 8 * w + 2 * qid;
    int m0 = 2 * w, m1 = 2 * w + 1;
    int e = 2 * lane;

    float wacc[4][4];
#pragma unroll
    for (int mt = 0; mt < 4; mt++) {
        float2 v0 = *(const float2*)&W1_0[(size_t)h * 4096 + (16 * mt + grp) * 64 + col0];
        float2 v1 = *(const float2*)&W1_0[(size_t)h * 4096 + (16 * mt + grp + 8) * 64 + col0];
        wacc[mt][0] = v0.x; wacc[mt][1] = v0.y;
        wacc[mt][2] = v1.x; wacc[mt][3] = v1.y;
    }
    if (tid < 64) sb1[tid] = b1_0[h * 64 + tid];
    float gR0 = gamma[h * 64 + e], gR1 = gamma[h * 64 + e + 1];
    float btR0 = beta[h * 64 + e], btR1 = beta[h * 64 + e + 1];
    float ls = fmaxf(lti[15] + (1.0f / 16.0f), 0.0f) * (1.0f / 64.0f);

    const float* pk = g_xk + (size_t)bh * NMB * 1024;
    const float* pq = g_xq + (size_t)bh * NMB * 1024;
    const float* pv = g_xv + (size_t)bh * NMB * 1024;
    const float* plr = g_lr + (size_t)bh * NMB * 16;
    uint32_t stile_u = (uint32_t)__cvta_generic_to_shared(stile);
    uint32_t slr_u   = (uint32_t)__cvta_generic_to_shared(slr2);

    uint32_t aoff = (uint32_t)((lane & 15) * STS2 + (lane >> 4) * 4) * 4u;

    scan_prefetch(pk, pq, pv, plr, 0, 0, stile_u, slr_u, tid);

    for (int n = 0; n < NMB; n++) {
        int st = n & 1;
#pragma unroll
        for (int mt = 0; mt < 4; mt++) {
            *(float2*)&sWp[(16 * mt + grp) * SWST + col0] =
                make_float2(wacc[mt][0], wacc[mt][1]);
            *(float2*)&sWp[(16 * mt + grp + 8) * SWST + col0] =
                make_float2(wacc[mt][2], wacc[mt][3]);
        }
        cpwait<0>();
        __syncthreads();                                   // sync1
        if (n + 1 < NMB)
            scan_prefetch(pk, pq, pv, plr, n + 1, st ^ 1, stile_u, slr_u, tid);

        float* sxk = stile + st * STAGEF;
        float* sxv = sxk + 2 * TILEF;
        uint32_t sxk_u = stile_u + (uint32_t)(st * STAGEF) * 4u;
        uint32_t sxq_u = sxk_u + TILEF * 4u;

        // ---- Z1 = xk@W, Zq = xq@W (A via ldmatrix.x4) ----
        float zkh[4] = {0, 0, 0, 0}, zkl[4] = {0, 0, 0, 0};
        float zqh[4] = {0, 0, 0, 0}, zql[4] = {0, 0, 0, 0};
#pragma unroll
        for (int kt = 0; kt < 8; kt++) {
            int k = 8 * kt;
            float b0r = sWp[(k + qid) * SWST + 8 * w + grp];
            float b1r = sWp[(k + qid + 4) * SWST + 8 * w + grp];
            uint32_t bhi[2], blo[2];
            bhi[0] = f2tf32(b0r); blo[0] = f2tf32(b0r - __uint_as_float(bhi[0]));
            bhi[1] = f2tf32(b1r); blo[1] = f2tf32(b1r - __uint_as_float(bhi[1]));
            uint32_t araw[4], ah[4];
            LDMX4(araw, sxk_u + aoff + k * 4);
#pragma unroll
            for (int i = 0; i < 4; i++) ah[i] = f2tf32(__uint_as_float(araw[i]));
            mma_tf32(zkl, ah, blo); mma_tf32(zkh, ah, bhi);
            LDMX4(araw, sxq_u + aoff + k * 4);
#pragma unroll
            for (int i = 0; i < 4; i++) ah[i] = f2tf32(__uint_as_float(araw[i]));
            mma_tf32(zql, ah, blo); mma_tf32(zqh, ah, bhi);
        }
        float bb0 = sb1[col0], bb1 = sb1[col0 + 1];
        float zk0 = zkh[0] + zkl[0] + bb0, zk1 = zkh[1] + zkl[1] + bb1;
        float zk2 = zkh[2] + zkl[2] + bb0, zk3 = zkh[3] + zkl[3] + bb1;
        float zq0 = zqh[0] + zql[0] + bb0, zq1 = zqh[1] + zql[1] + bb1;
        float zq2 = zqh[2] + zql[2] + bb0, zq3 = zqh[3] + zql[3] + bb1;

        size_t base = ((size_t)bh * NMB + n) * 1024;
        *(float2*)&g_zq[base + grp * 64 + col0]       = make_float2(zq0, zq1);
        *(float2*)&g_zq[base + (grp + 8) * 64 + col0] = make_float2(zq2, zq3);

        *(float2*)&szk[grp * STS2 + col0]       = make_float2(zk0, zk1);
        *(float2*)&szk[(grp + 8) * STS2 + col0] = make_float2(zk2, zk3);
        __syncthreads();                                   // sync2

        // ---- warp-local LN-L2 backward: warp w owns rows m0, m1 ----
        float2 za = *(const float2*)&szk[m0 * STS2 + e];
        float2 zb = *(const float2*)&szk[m1 * STS2 + e];
        float s1a = za.x + za.y, s2a = za.x * za.x + za.y * za.y;
        float s1b = zb.x + zb.y, s2b = zb.x * zb.x + zb.y * zb.y;
        wred4(s1a, s2a, s1b, s2b);
        float mu0 = s1a * (1.0f / 64.0f);
        float rs0 = rsqrtf(s2a * (1.0f / 64.0f) - mu0 * mu0 + 1e-5f);
        float mu1 = s1b * (1.0f / 64.0f);
        float rs1 = rsqrtf(s2b * (1.0f / 64.0f) - mu1 * mu1 + 1e-5f);
        float xh00 = (za.x - mu0) * rs0, xh01 = (za.y - mu0) * rs0;
        float xh10 = (zb.x - mu1) * rs1, xh11 = (zb.y - mu1) * rs1;
        float2 xv0 = *(const float2*)&sxv[m0 * STS2 + e];
        float2 xv1 = *(const float2*)&sxv[m1 * STS2 + e];
        float2 xk0v = *(const float2*)&sxk[m0 * STS2 + e];
        float2 xk1v = *(const float2*)&sxk[m1 * STS2 + e];
        float gy00 = (fmaf(gR0, xh00, btR0) - (xv0.x - xk0v.x)) * gR0;
        float gy01 = (fmaf(gR1, xh01, btR1) - (xv0.y - xk0v.y)) * gR1;
        float gy10 = (fmaf(gR0, xh10, btR0) - (xv1.x - xk1v.x)) * gR0;
        float gy11 = (fmaf(gR1, xh11, btR1) - (xv1.y - xk1v.y)) * gR1;
        float t1a = gy00 + gy01, t2a = gy00 * xh00 + gy01 * xh01;
        float t1b = gy10 + gy11, t2b = gy10 * xh10 + gy11 * xh11;
        wred4(t1a, t2a, t1b, t2b);
        float sc0 = rs0 * (1.0f / 64.0f), sc1 = rs1 * (1.0f / 64.0f);
        float gr00 = (64.0f * gy00 - t1a - xh00 * t2a) * sc0;
        float gr01 = (64.0f * gy01 - t1a - xh01 * t2a) * sc0;
        float gr10 = (64.0f * gy10 - t1b - xh10 * t2b) * sc1;
        float gr11 = (64.0f * gy11 - t1b - xh11 * t2b) * sc1;

        *(float2*)&g_grad[base + m0 * 64 + e] = make_float2(gr00, gr01);
        *(float2*)&g_grad[base + m1 * 64 + e] = make_float2(gr10, gr11);

        float lr0 = ls * slr2[st * 16 + m0];
        float lr1 = ls * slr2[st * 16 + m1];
        *(float2*)&sgl[m0 * SGST + e] = make_float2(-lr0 * gr00, -lr0 * gr01);
        *(float2*)&sgl[m1 * SGST + e] = make_float2(-lr1 * gr10, -lr1 * gr11);
        __syncthreads();                                   // sync3

        // ---- W += xk^T @ sgl ----
#pragma unroll
        for (int kt = 0; kt < 2; kt++) {
            int k = 8 * kt;
            float b0r = sgl[(k + qid) * SGST + 8 * w + grp];
            float b1r = sgl[(k + qid + 4) * SGST + 8 * w + grp];
            uint32_t bhi[2], blo[2];
            bhi[0] = f2tf32(b0r); blo[0] = f2tf32(b0r - __uint_as_float(bhi[0]));
            bhi[1] = f2tf32(b1r); blo[1] = f2tf32(b1r - __uint_as_float(bhi[1]));
#pragma unroll
            for (int mt = 0; mt < 4; mt++) {
                float ar[4];
                uint32_t ah[4];
                ar[0] = sxk[(k + qid) * STS2 + 16 * mt + grp];
                ar[1] = sxk[(k + qid) * STS2 + 16 * mt + grp + 8];
                ar[2] = sxk[(k + qid + 4) * STS2 + 16 * mt + grp];
                ar[3] = sxk[(k + qid + 4) * STS2 + 16 * mt + grp + 8];
                cvt4(ar, ah);
                mma_tf32(wacc[mt], ah, blo);
                mma_tf32(wacc[mt], ah, bhi);
            }
        }
        if (tid < 64) {
            float s = 0.0f;
#pragma unroll
            for (int mm2 = 0; mm2 < 16; mm2++) s += sgl[mm2 * SGST + tid];
            sb1[tid] += s;
        }
    }
}

// ---------------- fused: 148 CTAs = 48 scan (dedicated SMs) + 100 gemm ----
__global__ __launch_bounds__(256) void fused_scan_gate(
    const float* __restrict__ hs, const float* __restrict__ wg,
    const float* __restrict__ W1_0, const float* __restrict__ b1_0,
    const float* __restrict__ gamma, const float* __restrict__ beta,
    const float* __restrict__ lti)
{
    if (blockIdx.x < NCHAIN) {
        scan_body_tc(blockIdx.x, W1_0, b1_0, gamma, beta, lti);
    } else {
        for (int t = blockIdx.x - NCHAIN; t < 384; t += 100)
            gemm_body(hs, wg, g_gate, t % 6, t / 6, 1);
    }
}

// ---------------- parallel epilogue: y = xq + LN(Zq - coef@grad) ----------
__global__ __launch_bounds__(256) void epilogue_y(
    const float* __restrict__ gamma, const float* __restrict__ beta,
    const float* __restrict__ lti)
{
    int blk = blockIdx.x;
    int bh = blk >> 7;
    int n  = blk & 127;
    int b = bh / NHEAD, h = bh % NHEAD;

    __shared__ float sxq[16 * STS2], sxk[16 * STS2], sgr[16 * STS2];
    __shared__ float scoef[256], stok[16], slr[16], sg[64], sbt[64];

    int tid = threadIdx.x;
    int row = tid >> 4, col = (tid & 15) * 4;
    size_t base = ((size_t)bh * NMB + n) * 1024;
    int gi = row * 64 + col;
    *(float4*)&sxq[row * STS2 + col] = *(const float4*)&g_xq[base + gi];
    *(float4*)&sxk[row * STS2 + col] = *(const float4*)&g_xk[base + gi];
    *(float4*)&sgr[row * STS2 + col] = *(const float4*)&g_grad[base + gi];
    if (tid < 16) {
        stok[tid] = fmaxf(lti[tid] + 1.0f / (float)(tid + 1), 0.0f);
        slr[tid]  = g_lr[(size_t)bh * NMB * 16 + n * 16 + tid];
    }
    if (tid < 64) {
        sg[tid]  = gamma[h * 64 + tid];
        sbt[tid] = beta[h * 64 + tid];
    }

    // load Zq directly to registers (global layout == consumption layout)
    int w = tid >> 5, lane = tid & 31;
    int m0 = 2 * w, m1 = 2 * w + 1;
    int e = 2 * lane;
    float2 z0 = *(const float2*)&g_zq[base + m0 * 64 + e];
    float2 z1 = *(const float2*)&g_zq[base + m1 * 64 + e];
    __syncthreads();

    {
        int mm = tid >> 4, nn = tid & 15;
        if (nn <= mm) {     // tril: upper entries are never read as nonzero
            float a = 0.0f;
#pragma unroll
            for (int d = 0; d < 64; d += 4) {
                float4 qv = *(const float4*)&sxq[mm * STS2 + d];
                float4 kv = *(const float4*)&sxk[nn * STS2 + d];
                a = fmaf(qv.x, kv.x, a);
                a = fmaf(qv.y, kv.y, a);
                a = fmaf(qv.z, kv.z, a);
                a = fmaf(qv.w, kv.w, a);
            }
            scoef[tid] = stok[mm] * slr[nn] * (1.0f / 64.0f) * (a + 1.0f);
        } else {
            scoef[tid] = 0.0f;
        }
    }
    __syncthreads();

    float zq00 = z0.x, zq01 = z0.y, zq10 = z1.x, zq11 = z1.y;
#pragma unroll
    for (int nn = 0; nn < 16; nn++) {
        float c0 = scoef[m0 * 16 + nn];
        float c1 = scoef[m1 * 16 + nn];
        float2 gv = *(const float2*)&sgr[nn * STS2 + e];
        zq00 = fmaf(-c0, gv.x, zq00); zq01 = fmaf(-c0, gv.y, zq01);
        zq10 = fmaf(-c1, gv.x, zq10); zq11 = fmaf(-c1, gv.y, zq11);
    }
    float s1a = zq00 + zq01, s2a = zq00 * zq00 + zq01 * zq01;
    float s1b = zq10 + zq11, s2b = zq10 * zq10 + zq11 * zq11;
    wred4(s1a, s2a, s1b, s2b);
    float mu0 = s1a * (1.0f / 64.0f);
    float rs0 = rsqrtf(s2a * (1.0f / 64.0f) - mu0 * mu0 + 1e-5f);
    float mu1 = s1b * (1.0f / 64.0f);
    float rs1 = rsqrtf(s2b * (1.0f / 64.0f) - mu1 * mu1 + 1e-5f);
    float g0 = sg[e], g1 = sg[e + 1], bt0 = sbt[e], bt1 = sbt[e + 1];
    float2 qx0 = *(const float2*)&sxq[m0 * STS2 + e];
    float2 qx1 = *(const float2*)&sxq[m1 * STS2 + e];
    float y00 = qx0.x + fmaf((zq00 - mu0) * rs0, g0, bt0);
    float y01 = qx0.y + fmaf((zq01 - mu0) * rs0, g1, bt1);
    float y10 = qx1.x + fmaf((zq10 - mu1) * rs1, g0, bt0);
    float y11 = qx1.y + fmaf((zq11 - mu1) * rs1, g1, bt1);
    size_t or0 = ((size_t)(b * NSEQ + n * MM + m0)) * HH + h * HDIM + e;
    size_t or1 = ((size_t)(b * NSEQ + n * MM + m1)) * HH + h * HDIM + e;
    *(float2*)&g_y[or0] = make_float2(y00, y01);
    *(float2*)&g_y[or1] = make_float2(y10, y11);
}

// ------- post-norm + gate multiply, 192 threads, float4 I/O --------------
__global__ __launch_bounds__(192) void postnorm_kernel(
    const float* __restrict__ pns, const float* __restrict__ pnb)
{
    int row = blockIdx.x;
    int tid = threadIdx.x;
    const float* y = g_y + (size_t)row * HH;
    float4 v = *(const float4*)(y + tid * 4);
    float s1 = v.x + v.y + v.z + v.w;
    float s2 = v.x * v.x + v.y * v.y + v.z * v.z + v.w * v.w;
    wred2(s1, s2);
    __shared__ float r1[6], r2[6];
    int wid = tid >> 5, ln = tid & 31;
    if (ln == 0) { r1[wid] = s1; r2[wid] = s2; }
    __syncthreads();
    float a = 0.0f, bsum = 0.0f;
#pragma unroll
    for (int i = 0; i < 6; i++) { a += r1[i]; bsum += r2[i]; }
    float mu = a * (1.0f / 768.0f);
    float rstd = rsqrtf(bsum * (1.0f / 768.0f) - mu * mu + 1e-5f);
    float4 sc = *(const float4*)(pns + tid * 4);
    float4 bi = *(const float4*)(pnb + tid * 4);
    float4 gt = *(const float4*)(g_gate + (size_t)row * HH + tid * 4);
    float4 o;
    o.x = gt.x * fmaf((v.x - mu) * rstd, sc.x, bi.x);
    o.y = gt.y * fmaf((v.y - mu) * rstd, sc.y, bi.y);
    o.z = gt.z * fmaf((v.z - mu) * rstd, sc.z, bi.z);
    o.w = gt.w * fmaf((v.w - mu) * rstd, sc.w, bi.w);
    *(float4*)(g_tmp + (size_t)row * HH + tid * 4) = o;
}

// ---------------- launch --------------------------------------------------
extern "C" void kernel_launch(void* const* d_in, const int* in_sizes, int n_in,
                              void* d_out, int out_size)
{
    const float* hs  = (const float*)d_in[0];
    const int*   pid = (const int*)  d_in[1];
    const float* wq  = (const float*)d_in[2];
    const float* wv  = (const float*)d_in[3];
    const float* wo  = (const float*)d_in[4];
    const float* wg  = (const float*)d_in[5];
    const float* cqk = (const float*)d_in[6];
    const float* cqb = (const float*)d_in[7];
    const float* ckk = (const float*)d_in[8];
    const float* ckb = (const float*)d_in[9];
    const float* lrw = (const float*)d_in[10];
    const float* lrb = (const float*)d_in[11];
    const float* lti = (const float*)d_in[12];
    const float* gam = (const float*)d_in[13];
    const float* bet = (const float*)d_in[14];
    const float* pns = (const float*)d_in[15];
    const float* pnb = (const float*)d_in[16];
    const float* W10 = (const float*)d_in[17];
    const float* b10 = (const float*)d_in[18];
    float* out = (float*)d_out;

    cudaFuncSetAttribute(gemm_tc, cudaFuncAttributeMaxDynamicSharedMemorySize,
                         GEMM_SMEM);
    cudaFuncSetAttribute(gemm_qv, cudaFuncAttributeMaxDynamicSharedMemorySize,
                         GEMM_SMEM);
    cudaFuncSetAttribute(fused_scan_gate,
                         cudaFuncAttributeMaxDynamicSharedMemorySize, GEMM_SMEM);

    dim3 qvgrid(12, BNROWS / 128);       // wq + wv combined
    dim3 ggrid(HH / 128, BNROWS / 128);  // (6, 64)

    gemm_qv<<<qvgrid, 256, GEMM_SMEM>>>(hs, wq, wv);

    convrope_kernel<<<BNROWS / 4, 384>>>(pid, cqk, cqb, ckk, ckb, hs, lrw, lrb);

    fused_scan_gate<<<148, 256, GEMM_SMEM>>>(hs, wg, W10, b10, gam, bet, lti);

    epilogue_y<<<NCHAIN * NMB, 256>>>(gam, bet, lti);

    postnorm_kernel<<<BNROWS, 192>>>(pns, pnb);

    gemm_tc<<<ggrid, 256, GEMM_SMEM>>>(wo, nullptr, out, 1, 3, 0);  // final
}